// round 11
// baseline (speedup 1.0000x reference)
#include <cuda_runtime.h>
#include <cuda_fp16.h>
#include <cstdint>

#define HIDDEN 256
#define HEADS 8
#define MAXN 50000
#define MAXE 800000

// ---------------- scratch ----------------
// Permuted fp16 layout (per row of 256 halfs): half idx p, block n0=(p&128):
//   jj = p & 127; feat = n0 + (jj&1)*64 + (jj>>1)
// => word w: w<64 -> feats (w, w+64); w>=64 -> feats (w+64, w+128).
//   Both feats of a word share head (w%8); lane l reads words c*32+l -> head l%8.
__device__ __half g_qh[(size_t)MAXN * HIDDEN];
__device__ __half g_kh[(size_t)MAXN * HIDDEN];
__device__ __half g_vh[(size_t)MAXN * HIDDEN];
__device__ __half g_aoh[(size_t)MAXN * HIDDEN];
__device__ int    g_deg[MAXN];
__device__ int    g_offs[MAXN + 1];
__device__ int    g_cursor[MAXN];
__device__ int    g_ccol[MAXE];

// ---------------- CSR build ----------------
__global__ void count_deg_kernel(const int* __restrict__ row, int e) {
    int i = blockIdx.x * blockDim.x + threadIdx.x;
    if (i < e) atomicAdd(&g_deg[row[i]], 1);
}

__global__ void scan_kernel(int n) {
    __shared__ int wsum[32];
    int lane = threadIdx.x & 31;
    int wid  = threadIdx.x >> 5;
    int carry = 0;
    for (int base = 0; base < n; base += 1024) {
        int i = base + (int)threadIdx.x;
        int v = (i < n) ? g_deg[i] : 0;
        int x = v;
        #pragma unroll
        for (int d = 1; d < 32; d <<= 1) {
            int y = __shfl_up_sync(0xffffffffu, x, d);
            if (lane >= d) x += y;
        }
        if (lane == 31) wsum[wid] = x;
        __syncthreads();
        if (wid == 0) {
            int wv = wsum[lane];
            #pragma unroll
            for (int d = 1; d < 32; d <<= 1) {
                int y = __shfl_up_sync(0xffffffffu, wv, d);
                if (lane >= d) wv += y;
            }
            wsum[lane] = wv;
        }
        __syncthreads();
        int inc = x + (wid > 0 ? wsum[wid - 1] : 0) + carry;
        if (i < n) {
            int excl = inc - v;
            g_offs[i]   = excl;
            g_cursor[i] = excl;
        }
        carry += wsum[31];
        __syncthreads();
    }
    if (threadIdx.x == 0) g_offs[n] = carry;
}

__global__ void scatter_kernel(const int* __restrict__ row, const int* __restrict__ col, int e) {
    int i = blockIdx.x * blockDim.x + threadIdx.x;
    if (i < e) {
        int slot = atomicAdd(&g_cursor[row[i]], 1);
        g_ccol[slot] = col[i];
    }
}

// ================ shared GEMM pieces ================
__device__ __forceinline__ uint32_t packh2(float x, float y) {
    __half2 h = __halves2half2(__float2half_rn(x), __float2half_rn(y));
    return *(uint32_t*)&h;
}
__device__ __forceinline__ uint32_t packlo2(float x, float y, uint32_t h) {
    __half2 hh = *(__half2*)&h;
    float rx = x - __half2float(__low2half(hh));
    float ry = y - __half2float(__high2half(hh));
    return packh2(rx, ry);
}

#define MMA_F16(ACC, AV, B0, B1)                                           \
    asm volatile(                                                          \
        "mma.sync.aligned.m16n8k16.row.col.f32.f16.f16.f32 "              \
        "{%0,%1,%2,%3}, {%4,%5,%6,%7}, {%8,%9}, {%0,%1,%2,%3};"           \
        : "+f"(ACC[0]), "+f"(ACC[1]), "+f"(ACC[2]), "+f"(ACC[3])          \
        : "r"(AV.x), "r"(AV.y), "r"(AV.z), "r"(AV.w),                     \
          "r"(B0), "r"(B1))

// ================ QKV GEMM: BM=128 BN=64, warp tile 32x32, 3 CTA/SM ========
// fp32 A, split A+B (3-term fp16), fp16 permuted out.
#define QST_AH 0
#define QST_AL 4096
#define QST_BH 8192
#define QST_BL 10240
#define QST_SZ 12288

__global__ void __launch_bounds__(256, 3) gemm_qkv_kernel(
    const float* __restrict__ A,
    const float* __restrict__ W0, const float* __restrict__ W1, const float* __restrict__ W2,
    const float* __restrict__ b0_, const float* __restrict__ b1_, const float* __restrict__ b2_,
    __half* __restrict__ QH, __half* __restrict__ KH, __half* __restrict__ VH,
    int M, float scale0)
{
    __shared__ __align__(16) unsigned char sm[2][QST_SZ];

    const int z = blockIdx.z;
    const float* W    = (z == 0) ? W0 : (z == 1) ? W1 : W2;
    const float* bias = (z == 0) ? b0_ : (z == 1) ? b1_ : b2_;
    __half* H         = (z == 0) ? QH : (z == 1) ? KH : VH;
    const float scale = (z == 0) ? scale0 : 1.f;

    const int tid  = threadIdx.x;
    const int lane = tid & 31;
    const int warp = tid >> 5;
    const int g    = lane >> 2;
    const int tig  = lane & 3;
    const int mi   = warp >> 1;          // 0..3
    const int ni   = warp & 1;           // 0..1
    const int wm   = mi * 32;
    const int wn   = ni * 32;

    const int m0 = blockIdx.x * 128;
    const int yb = blockIdx.y;           // 0..3, 64-wide permuted output slot block

    // ---- fill mapping ----
    const int ftr = warp;                // A tile 0..7, B tile 0..7
    const int fl  = lane;
    const int arow_lo = m0 + ftr * 16 + g;
    const int arow_hi = arow_lo + 8;
    const bool vlo = arow_lo < M, vhi = arow_hi < M;
    const float* Ap_ll = A + (size_t)arow_lo * HIDDEN + 2 * tig;
    const float* Ap_hl = A + (size_t)arow_hi * HIDDEN + 2 * tig;

    // W row via output-slot permutation: p = yb*64 + (ftr*8+g)
    const int pB  = yb * 64 + ftr * 8 + g;
    const int wr  = (pB & 128) + (((pB & 127) & 1) << 6) + ((pB & 127) >> 1);
    const float* Wp0 = W + (size_t)wr * HIDDEN + 2 * tig;

    float2 xa0, xa1, xa2, xa3, xb0, xb1;
    const float2 Z2 = make_float2(0.f, 0.f);

    xa0 = vlo ? *(const float2*)(Ap_ll)     : Z2;
    xa1 = vhi ? *(const float2*)(Ap_hl)     : Z2;
    xa2 = vlo ? *(const float2*)(Ap_ll + 8) : Z2;
    xa3 = vhi ? *(const float2*)(Ap_hl + 8) : Z2;
    xb0 = *(const float2*)(Wp0);
    xb1 = *(const float2*)(Wp0 + 8);

    float acc[2][4][4];
    #pragma unroll
    for (int mt = 0; mt < 2; mt++)
        #pragma unroll
        for (int nt = 0; nt < 4; nt++)
            #pragma unroll
            for (int r = 0; r < 4; r++) acc[mt][nt][r] = 0.f;

    {
        unsigned char* st = sm[0];
        uint4 h, l;
        h.x = packh2(xa0.x, xa0.y); l.x = packlo2(xa0.x, xa0.y, h.x);
        h.y = packh2(xa1.x, xa1.y); l.y = packlo2(xa1.x, xa1.y, h.y);
        h.z = packh2(xa2.x, xa2.y); l.z = packlo2(xa2.x, xa2.y, h.z);
        h.w = packh2(xa3.x, xa3.y); l.w = packlo2(xa3.x, xa3.y, h.w);
        *(uint4*)(st + QST_AH + ftr * 512 + fl * 16) = h;
        *(uint4*)(st + QST_AL + ftr * 512 + fl * 16) = l;
        uint2 bh, bl;
        bh.x = packh2(xb0.x, xb0.y); bl.x = packlo2(xb0.x, xb0.y, bh.x);
        bh.y = packh2(xb1.x, xb1.y); bl.y = packlo2(xb1.x, xb1.y, bh.y);
        *(uint2*)(st + QST_BH + ftr * 256 + fl * 8) = bh;
        *(uint2*)(st + QST_BL + ftr * 256 + fl * 8) = bl;
    }
    __syncthreads();

    #pragma unroll 1
    for (int it = 0; it < 16; it++) {
        if (it + 1 < 16) {
            int ko = (it + 1) * 16;
            xa0 = vlo ? *(const float2*)(Ap_ll + ko)     : Z2;
            xa1 = vhi ? *(const float2*)(Ap_hl + ko)     : Z2;
            xa2 = vlo ? *(const float2*)(Ap_ll + ko + 8) : Z2;
            xa3 = vhi ? *(const float2*)(Ap_hl + ko + 8) : Z2;
            xb0 = *(const float2*)(Wp0 + ko);
            xb1 = *(const float2*)(Wp0 + ko + 8);
        }

        {
            const unsigned char* st = sm[it & 1];
            uint4 ah[2], al[2];
            #pragma unroll
            for (int mt = 0; mt < 2; mt++) {
                int tr = mi * 2 + mt;
                ah[mt] = *(const uint4*)(st + QST_AH + tr * 512 + lane * 16);
                al[mt] = *(const uint4*)(st + QST_AL + tr * 512 + lane * 16);
            }
            #pragma unroll
            for (int nt = 0; nt < 4; nt++) {
                int tn = ni * 4 + nt;
                uint2 bh = *(const uint2*)(st + QST_BH + tn * 256 + lane * 8);
                uint2 bl = *(const uint2*)(st + QST_BL + tn * 256 + lane * 8);
                MMA_F16(acc[0][nt], al[0], bh.x, bh.y);
                MMA_F16(acc[1][nt], al[1], bh.x, bh.y);
                MMA_F16(acc[0][nt], ah[0], bl.x, bl.y);
                MMA_F16(acc[1][nt], ah[1], bl.x, bl.y);
                MMA_F16(acc[0][nt], ah[0], bh.x, bh.y);
                MMA_F16(acc[1][nt], ah[1], bh.x, bh.y);
            }
        }

        if (it + 1 < 16) {
            unsigned char* st = sm[(it + 1) & 1];
            uint4 h, l;
            h.x = packh2(xa0.x, xa0.y); l.x = packlo2(xa0.x, xa0.y, h.x);
            h.y = packh2(xa1.x, xa1.y); l.y = packlo2(xa1.x, xa1.y, h.y);
            h.z = packh2(xa2.x, xa2.y); l.z = packlo2(xa2.x, xa2.y, h.z);
            h.w = packh2(xa3.x, xa3.y); l.w = packlo2(xa3.x, xa3.y, h.w);
            *(uint4*)(st + QST_AH + ftr * 512 + fl * 16) = h;
            *(uint4*)(st + QST_AL + ftr * 512 + fl * 16) = l;
            uint2 bh, bl;
            bh.x = packh2(xb0.x, xb0.y); bl.x = packlo2(xb0.x, xb0.y, bh.x);
            bh.y = packh2(xb1.x, xb1.y); bl.y = packlo2(xb1.x, xb1.y, bh.y);
            *(uint2*)(st + QST_BH + ftr * 256 + fl * 8) = bh;
            *(uint2*)(st + QST_BL + ftr * 256 + fl * 8) = bl;
        }
        __syncthreads();
    }

    // fp16 permuted epilogue: contiguous __half2 at half-index p = yb*64 + jl
    #pragma unroll
    for (int mt = 0; mt < 2; mt++) {
        int r0 = m0 + wm + mt * 16 + g;
        #pragma unroll
        for (int nt = 0; nt < 4; nt++) {
            int jl = wn + nt * 8 + 2 * tig;      // local 0..63, even
            int p  = yb * 64 + jl;
            int f0 = (p & 128) + ((p & 127) >> 1);
            float bx = bias[f0];
            float by = bias[f0 + 64];
            if (r0 < M) {
                *(__half2*)(H + (size_t)r0 * HIDDEN + p) =
                    __halves2half2(__float2half_rn((acc[mt][nt][0] + bx) * scale),
                                   __float2half_rn((acc[mt][nt][1] + by) * scale));
            }
            if (r0 + 8 < M) {
                *(__half2*)(H + (size_t)(r0 + 8) * HIDDEN + p) =
                    __halves2half2(__float2half_rn((acc[mt][nt][2] + bx) * scale),
                                   __float2half_rn((acc[mt][nt][3] + by) * scale));
            }
        }
    }
}

// ================ O-proj GEMM: fp16 permuted A (exact), split B, 2-term ======
#define ST_AH 0
#define ST_AL 4096
#define ST_BH 8192
#define ST_BL 12288
#define ST_SZ 16384

__global__ void __launch_bounds__(256, 2) gemm_oproj_kernel(
    const __half* __restrict__ AH,
    const float* __restrict__ W, const float* __restrict__ bias,
    float* __restrict__ C, int M)
{
    __shared__ __align__(16) unsigned char sm[2][ST_SZ];

    const int tid  = threadIdx.x;
    const int lane = tid & 31;
    const int warp = tid >> 5;
    const int g    = lane >> 2;
    const int tig  = lane & 3;
    const int wm   = (warp >> 1) * 32;
    const int wn   = (warp & 1) * 64;

    const int m0 = blockIdx.x * 128;
    const int n0 = blockIdx.y * 128;

    const int ftr = tid >> 5;
    const int fl  = lane;
    const int arow_lo = m0 + ftr * 16 + g;
    const int arow_hi = arow_lo + 8;
    const bool vlo = arow_lo < M, vhi = arow_hi < M;
    const uint32_t* Aw_lo = (const uint32_t*)(AH + (size_t)arow_lo * HIDDEN);
    const uint32_t* Aw_hi = (const uint32_t*)(AH + (size_t)arow_hi * HIDDEN);

    const int wr0 = n0 + ftr * 8 + g;
    const int wr1 = n0 + (ftr + 8) * 8 + g;
    const float* Wr0 = W + (size_t)wr0 * HIDDEN;
    const float* Wr1 = W + (size_t)wr1 * HIDDEN;

    uint32_t xa0, xa1, xa2, xa3;
    float2 xb0, xb1, xb2, xb3;

    #define WPAIR(Wr, w) make_float2(Wr[(w) + (((w) >= 64) ? 64 : 0)],           \
                                     Wr[(w) + (((w) >= 64) ? 64 : 0) + 64])

    {
        int w0 = tig, w1 = tig + 4;
        xa0 = vlo ? Aw_lo[w0] : 0u;
        xa1 = vhi ? Aw_hi[w0] : 0u;
        xa2 = vlo ? Aw_lo[w1] : 0u;
        xa3 = vhi ? Aw_hi[w1] : 0u;
        xb0 = WPAIR(Wr0, w0); xb1 = WPAIR(Wr0, w1);
        xb2 = WPAIR(Wr1, w0); xb3 = WPAIR(Wr1, w1);
    }

    float acc[2][8][4];
    #pragma unroll
    for (int mt = 0; mt < 2; mt++)
        #pragma unroll
        for (int nt = 0; nt < 8; nt++)
            #pragma unroll
            for (int r = 0; r < 4; r++) acc[mt][nt][r] = 0.f;

    {
        unsigned char* st = sm[0];
        *(uint4*)(st + ST_AH + ftr * 512 + fl * 16) = make_uint4(xa0, xa1, xa2, xa3);
        uint2 bh0, bl0, bh1, bl1;
        bh0.x = packh2(xb0.x, xb0.y); bl0.x = packlo2(xb0.x, xb0.y, bh0.x);
        bh0.y = packh2(xb1.x, xb1.y); bl0.y = packlo2(xb1.x, xb1.y, bh0.y);
        bh1.x = packh2(xb2.x, xb2.y); bl1.x = packlo2(xb2.x, xb2.y, bh1.x);
        bh1.y = packh2(xb3.x, xb3.y); bl1.y = packlo2(xb3.x, xb3.y, bh1.y);
        *(uint2*)(st + ST_BH + ftr * 256 + fl * 8) = bh0;
        *(uint2*)(st + ST_BL + ftr * 256 + fl * 8) = bl0;
        *(uint2*)(st + ST_BH + (ftr + 8) * 256 + fl * 8) = bh1;
        *(uint2*)(st + ST_BL + (ftr + 8) * 256 + fl * 8) = bl1;
    }
    __syncthreads();

    #pragma unroll 1
    for (int it = 0; it < 16; it++) {
        if (it + 1 < 16) {
            int w0 = (it + 1) * 8 + tig, w1 = w0 + 4;
            xa0 = vlo ? Aw_lo[w0] : 0u;
            xa1 = vhi ? Aw_hi[w0] : 0u;
            xa2 = vlo ? Aw_lo[w1] : 0u;
            xa3 = vhi ? Aw_hi[w1] : 0u;
            xb0 = WPAIR(Wr0, w0); xb1 = WPAIR(Wr0, w1);
            xb2 = WPAIR(Wr1, w0); xb3 = WPAIR(Wr1, w1);
        }

        {
            const unsigned char* st = sm[it & 1];
            uint4 ah[2];
            #pragma unroll
            for (int mt = 0; mt < 2; mt++) {
                int tr = (wm >> 4) + mt;
                ah[mt] = *(const uint4*)(st + ST_AH + tr * 512 + lane * 16);
            }
            #pragma unroll
            for (int nt = 0; nt < 8; nt++) {
                int tn = (wn >> 3) + nt;
                uint2 bh = *(const uint2*)(st + ST_BH + tn * 256 + lane * 8);
                uint2 bl = *(const uint2*)(st + ST_BL + tn * 256 + lane * 8);
                MMA_F16(acc[0][nt], ah[0], bl.x, bl.y);
                MMA_F16(acc[1][nt], ah[1], bl.x, bl.y);
                MMA_F16(acc[0][nt], ah[0], bh.x, bh.y);
                MMA_F16(acc[1][nt], ah[1], bh.x, bh.y);
            }
        }

        if (it + 1 < 16) {
            unsigned char* st = sm[(it + 1) & 1];
            *(uint4*)(st + ST_AH + ftr * 512 + fl * 16) = make_uint4(xa0, xa1, xa2, xa3);
            uint2 bh0, bl0, bh1, bl1;
            bh0.x = packh2(xb0.x, xb0.y); bl0.x = packlo2(xb0.x, xb0.y, bh0.x);
            bh0.y = packh2(xb1.x, xb1.y); bl0.y = packlo2(xb1.x, xb1.y, bh0.y);
            bh1.x = packh2(xb2.x, xb2.y); bl1.x = packlo2(xb2.x, xb2.y, bh1.x);
            bh1.y = packh2(xb3.x, xb3.y); bl1.y = packlo2(xb3.x, xb3.y, bh1.y);
            *(uint2*)(st + ST_BH + ftr * 256 + fl * 8) = bh0;
            *(uint2*)(st + ST_BL + ftr * 256 + fl * 8) = bl0;
            *(uint2*)(st + ST_BH + (ftr + 8) * 256 + fl * 8) = bh1;
            *(uint2*)(st + ST_BL + (ftr + 8) * 256 + fl * 8) = bl1;
        }
        __syncthreads();
    }
    #undef WPAIR

    // fp32 epilogue
    #pragma unroll
    for (int mt = 0; mt < 2; mt++) {
        int r0 = m0 + wm + mt * 16 + g;
        #pragma unroll
        for (int nt = 0; nt < 8; nt++) {
            int c = n0 + wn + nt * 8 + 2 * tig;
            float bx = bias[c], by = bias[c + 1];
            if (r0 < M) {
                float2 o0;
                o0.x = acc[mt][nt][0] + bx;
                o0.y = acc[mt][nt][1] + by;
                *(float2*)(C + (size_t)r0 * HIDDEN + c) = o0;
            }
            if (r0 + 8 < M) {
                float2 o1;
                o1.x = acc[mt][nt][2] + bx;
                o1.y = acc[mt][nt][3] + by;
                *(float2*)(C + (size_t)(r0 + 8) * HIDDEN + c) = o1;
            }
        }
    }
}

// ---------------- attention: one warp per node, all-fp16, 8-edge unroll -----
__global__ void __launch_bounds__(256) attn_kernel(int n) {
    int gw   = (blockIdx.x * blockDim.x + threadIdx.x) >> 5;
    int lane = threadIdx.x & 31;
    if (gw >= n) return;
    const int i = gw;
    const int start = g_offs[i];
    const int end   = g_offs[i + 1];

    const __half2* QB = (const __half2*)g_qh;
    const __half2* KB = (const __half2*)g_kh;
    const __half2* VB = (const __half2*)g_vh;

    float2 ql[4];
    #pragma unroll
    for (int c = 0; c < 4; c++)
        ql[c] = __half22float2(QB[(size_t)i * 128 + c * 32 + lane]);

    float m = __int_as_float(0xff800000);
    float d = 0.f;
    float2 acc[4] = {};

    int p = start;
    for (; p + 7 < end; p += 8) {
        int cn[8];
        #pragma unroll
        for (int e = 0; e < 8; e++) cn[e] = g_ccol[p + e];

        float s[8] = {0.f, 0.f, 0.f, 0.f, 0.f, 0.f, 0.f, 0.f};
        #pragma unroll
        for (int c = 0; c < 4; c++) {
            int o = c * 32 + lane;
            #pragma unroll
            for (int e = 0; e < 8; e++) {
                float2 kf = __half22float2(__ldg(KB + (size_t)cn[e] * 128 + o));
                s[e] += ql[c].x * kf.x + ql[c].y * kf.y;
            }
        }
        #pragma unroll
        for (int e = 0; e < 8; e++) {
            s[e] += __shfl_xor_sync(0xffffffffu, s[e], 16);
            s[e] += __shfl_xor_sync(0xffffffffu, s[e], 8);
        }

        float m2 = m;
        #pragma unroll
        for (int e = 0; e < 8; e++) m2 = fmaxf(m2, s[e]);
        float cf = __expf(m - m2);
        float w[8], sw = 0.f;
        #pragma unroll
        for (int e = 0; e < 8; e++) { w[e] = __expf(s[e] - m2); sw += w[e]; }
        d = d * cf + sw;
        m = m2;

        #pragma unroll
        for (int c = 0; c < 4; c++) {
            int o = c * 32 + lane;
            float tx = acc[c].x * cf, ty = acc[c].y * cf;
            #pragma unroll
            for (int e = 0; e < 8; e++) {
                float2 vf = __half22float2(__ldg(VB + (size_t)cn[e] * 128 + o));
                tx += w[e] * vf.x;
                ty += w[e] * vf.y;
            }
            acc[c].x = tx; acc[c].y = ty;
        }
    }
    for (; p < end; p++) {
        int c0 = g_ccol[p];
        float s0 = 0.f;
        #pragma unroll
        for (int c = 0; c < 4; c++) {
            float2 kf = __half22float2(__ldg(KB + (size_t)c0 * 128 + c * 32 + lane));
            s0 += ql[c].x * kf.x + ql[c].y * kf.y;
        }
        s0 += __shfl_xor_sync(0xffffffffu, s0, 16);
        s0 += __shfl_xor_sync(0xffffffffu, s0, 8);
        float m2 = fmaxf(m, s0);
        float cf = __expf(m - m2);
        float w0 = __expf(s0 - m2);
        d = d * cf + w0;
        m = m2;
        #pragma unroll
        for (int c = 0; c < 4; c++) {
            float2 vf = __half22float2(__ldg(VB + (size_t)c0 * 128 + c * 32 + lane));
            acc[c].x = acc[c].x * cf + w0 * vf.x;
            acc[c].y = acc[c].y * cf + w0 * vf.y;
        }
    }

    float rd = (end > start) ? 1.f / d : 0.f;
    __half2* AO = (__half2*)g_aoh;
    #pragma unroll
    for (int c = 0; c < 4; c++) {
        AO[(size_t)i * 128 + c * 32 + lane] =
            __halves2half2(__float2half_rn(acc[c].x * rd),
                           __float2half_rn(acc[c].y * rd));
    }
}

// ---------------- launch ----------------
extern "C" void kernel_launch(void* const* d_in, const int* in_sizes, int n_in,
                              void* d_out, int out_size) {
    const float* h   = (const float*)d_in[0];
    const int*   row = (const int*)d_in[1];
    const int*   col = (const int*)d_in[2];
    const float* Wq  = (const float*)d_in[3];
    const float* bq  = (const float*)d_in[4];
    const float* Wk  = (const float*)d_in[5];
    const float* bk  = (const float*)d_in[6];
    const float* Wv  = (const float*)d_in[7];
    const float* bv  = (const float*)d_in[8];
    const float* Wo  = (const float*)d_in[9];
    const float* bo  = (const float*)d_in[10];
    float* out = (float*)d_out;

    const int N = in_sizes[0] / HIDDEN;
    const int E = in_sizes[1];

    __half *pqh, *pkh, *pvh, *paoh;
    int *pdeg;
    cudaGetSymbolAddress((void**)&pqh, g_qh);
    cudaGetSymbolAddress((void**)&pkh, g_kh);
    cudaGetSymbolAddress((void**)&pvh, g_vh);
    cudaGetSymbolAddress((void**)&paoh, g_aoh);
    cudaGetSymbolAddress((void**)&pdeg, g_deg);

    static cudaStream_t s2 = nullptr;
    static cudaEvent_t evFork = nullptr, evJoin = nullptr;
    if (!s2) {
        cudaStreamCreateWithFlags(&s2, cudaStreamNonBlocking);
        cudaEventCreateWithFlags(&evFork, cudaEventDisableTiming);
        cudaEventCreateWithFlags(&evJoin, cudaEventDisableTiming);
    }

    // fork: CSR build on s2, QKV GEMM on main stream
    cudaEventRecord(evFork, 0);
    cudaStreamWaitEvent(s2, evFork, 0);
    cudaMemsetAsync(pdeg, 0, (size_t)N * sizeof(int), s2);
    count_deg_kernel<<<(E + 255) / 256, 256, 0, s2>>>(row, E);
    scan_kernel<<<1, 1024, 0, s2>>>(N);
    scatter_kernel<<<(E + 255) / 256, 256, 0, s2>>>(row, col, E);
    cudaEventRecord(evJoin, s2);

    const float scaling = 0.17677669529663687f;  // 32^-0.5
    dim3 gqkv((N + 127) / 128, 4, 3);
    gemm_qkv_kernel<<<gqkv, 256>>>(h, Wq, Wk, Wv, bq, bk, bv,
                                   pqh, pkh, pvh, N, scaling);

    cudaStreamWaitEvent(0, evJoin, 0);
    attn_kernel<<<(N + 7) / 8, 256>>>(N);

    dim3 go((N + 127) / 128, HIDDEN / 128, 1);
    gemm_oproj_kernel<<<go, 256>>>(paoh, Wo, bo, out, N);
}

// round 12
// speedup vs baseline: 1.1749x; 1.1749x over previous
#include <cuda_runtime.h>
#include <cuda_fp16.h>
#include <cstdint>

#define HIDDEN 256
#define HEADS 8
#define MAXN 50000
#define MAXE 800000

// ---------------- scratch ----------------
// Permuted fp16 layout (per row of 256 halfs): half idx p, block n0=(p&128):
//   jj = p & 127; feat = n0 + (jj&1)*64 + (jj>>1)
// => word w: w<64 -> feats (w, w+64); w>=64 -> feats (w+64, w+128).
//   Both feats of a word share head (w%8); lane l reads words c*32+l -> head l%8.
__device__ __half g_qh[(size_t)MAXN * HIDDEN];
__device__ __half g_kh[(size_t)MAXN * HIDDEN];
__device__ __half g_vh[(size_t)MAXN * HIDDEN];
__device__ __half g_aoh[(size_t)MAXN * HIDDEN];
__device__ int    g_deg[MAXN];
__device__ int    g_offs[MAXN + 1];
__device__ int    g_cursor[MAXN];
__device__ int    g_ccol[MAXE];

// ---------------- CSR build ----------------
__global__ void count_deg_kernel(const int* __restrict__ row, int e) {
    int i = blockIdx.x * blockDim.x + threadIdx.x;
    if (i < e) atomicAdd(&g_deg[row[i]], 1);
}

__global__ void scan_kernel(int n) {
    __shared__ int wsum[32];
    int lane = threadIdx.x & 31;
    int wid  = threadIdx.x >> 5;
    int carry = 0;
    for (int base = 0; base < n; base += 1024) {
        int i = base + (int)threadIdx.x;
        int v = (i < n) ? g_deg[i] : 0;
        int x = v;
        #pragma unroll
        for (int d = 1; d < 32; d <<= 1) {
            int y = __shfl_up_sync(0xffffffffu, x, d);
            if (lane >= d) x += y;
        }
        if (lane == 31) wsum[wid] = x;
        __syncthreads();
        if (wid == 0) {
            int wv = wsum[lane];
            #pragma unroll
            for (int d = 1; d < 32; d <<= 1) {
                int y = __shfl_up_sync(0xffffffffu, wv, d);
                if (lane >= d) wv += y;
            }
            wsum[lane] = wv;
        }
        __syncthreads();
        int inc = x + (wid > 0 ? wsum[wid - 1] : 0) + carry;
        if (i < n) {
            int excl = inc - v;
            g_offs[i]   = excl;
            g_cursor[i] = excl;
        }
        carry += wsum[31];
        __syncthreads();
    }
    if (threadIdx.x == 0) g_offs[n] = carry;
}

__global__ void scatter_kernel(const int* __restrict__ row, const int* __restrict__ col, int e) {
    int i = blockIdx.x * blockDim.x + threadIdx.x;
    if (i < e) {
        int slot = atomicAdd(&g_cursor[row[i]], 1);
        g_ccol[slot] = col[i];
    }
}

// ================ shared GEMM pieces ================
__device__ __forceinline__ uint32_t packh2(float x, float y) {
    __half2 h = __halves2half2(__float2half_rn(x), __float2half_rn(y));
    return *(uint32_t*)&h;
}
__device__ __forceinline__ uint32_t packlo2(float x, float y, uint32_t h) {
    __half2 hh = *(__half2*)&h;
    float rx = x - __half2float(__low2half(hh));
    float ry = y - __half2float(__high2half(hh));
    return packh2(rx, ry);
}

#define MMA_F16(ACC, AV, B0, B1)                                           \
    asm volatile(                                                          \
        "mma.sync.aligned.m16n8k16.row.col.f32.f16.f16.f32 "              \
        "{%0,%1,%2,%3}, {%4,%5,%6,%7}, {%8,%9}, {%0,%1,%2,%3};"           \
        : "+f"(ACC[0]), "+f"(ACC[1]), "+f"(ACC[2]), "+f"(ACC[3])          \
        : "r"(AV.x), "r"(AV.y), "r"(AV.z), "r"(AV.w),                     \
          "r"(B0), "r"(B1))

// ================ QKV GEMM: fp16 A (2-term: ah*bl + ah*bh), permuted out ====
// BM=128 BN=128 BK=16, 8 warps, warp tile 32x64. Q/K/V outputs are fp16 anyway,
// so the A-lo term is below the output quantization floor.
#define QST_AH 0
#define QST_BH 4096
#define QST_BL 8192
#define QST_SZ 12288

__global__ void __launch_bounds__(256, 2) gemm_qkv_kernel(
    const float* __restrict__ A,
    const float* __restrict__ W0, const float* __restrict__ W1, const float* __restrict__ W2,
    const float* __restrict__ b0_, const float* __restrict__ b1_, const float* __restrict__ b2_,
    __half* __restrict__ QH, __half* __restrict__ KH, __half* __restrict__ VH,
    int M, float scale0)
{
    __shared__ __align__(16) unsigned char sm[2][QST_SZ];

    const int z = blockIdx.z;
    const float* W    = (z == 0) ? W0 : (z == 1) ? W1 : W2;
    const float* bias = (z == 0) ? b0_ : (z == 1) ? b1_ : b2_;
    __half* H         = (z == 0) ? QH : (z == 1) ? KH : VH;
    const float scale = (z == 0) ? scale0 : 1.f;

    const int tid  = threadIdx.x;
    const int lane = tid & 31;
    const int warp = tid >> 5;
    const int g    = lane >> 2;
    const int tig  = lane & 3;
    const int wm   = (warp >> 1) * 32;
    const int wn   = (warp & 1) * 64;

    const int m0 = blockIdx.x * 128;
    const int n0 = blockIdx.y * 128;

    const int ftr = tid >> 5;
    const int fl  = lane;
    const int arow_lo = m0 + ftr * 16 + g;
    const int arow_hi = arow_lo + 8;
    const bool vlo = arow_lo < M, vhi = arow_hi < M;
    const float* Ap_ll = A + (size_t)arow_lo * HIDDEN + 2 * tig;
    const float* Ap_hl = A + (size_t)arow_hi * HIDDEN + 2 * tig;

    // permuted W rows so the fp16 epilogue is contiguous
    const int jl0 = ftr * 8 + g;
    const int jl1 = (ftr + 8) * 8 + g;
    const int wr0 = n0 + ((jl0 & 1) << 6) + (jl0 >> 1);
    const int wr1 = n0 + ((jl1 & 1) << 6) + (jl1 >> 1);
    const float* Wp0 = W + (size_t)wr0 * HIDDEN + 2 * tig;
    const float* Wp1 = W + (size_t)wr1 * HIDDEN + 2 * tig;

    float2 xa0, xa1, xa2, xa3, xb0, xb1, xb2, xb3;
    const float2 Z2 = make_float2(0.f, 0.f);

    xa0 = vlo ? *(const float2*)(Ap_ll)     : Z2;
    xa1 = vhi ? *(const float2*)(Ap_hl)     : Z2;
    xa2 = vlo ? *(const float2*)(Ap_ll + 8) : Z2;
    xa3 = vhi ? *(const float2*)(Ap_hl + 8) : Z2;
    xb0 = *(const float2*)(Wp0);
    xb1 = *(const float2*)(Wp0 + 8);
    xb2 = *(const float2*)(Wp1);
    xb3 = *(const float2*)(Wp1 + 8);

    float acc[2][8][4];
    #pragma unroll
    for (int mt = 0; mt < 2; mt++)
        #pragma unroll
        for (int nt = 0; nt < 8; nt++)
            #pragma unroll
            for (int r = 0; r < 4; r++) acc[mt][nt][r] = 0.f;

    {
        unsigned char* st = sm[0];
        uint4 h;
        h.x = packh2(xa0.x, xa0.y);
        h.y = packh2(xa1.x, xa1.y);
        h.z = packh2(xa2.x, xa2.y);
        h.w = packh2(xa3.x, xa3.y);
        *(uint4*)(st + QST_AH + ftr * 512 + fl * 16) = h;
        uint2 bh0, bl0, bh1, bl1;
        bh0.x = packh2(xb0.x, xb0.y); bl0.x = packlo2(xb0.x, xb0.y, bh0.x);
        bh0.y = packh2(xb1.x, xb1.y); bl0.y = packlo2(xb1.x, xb1.y, bh0.y);
        bh1.x = packh2(xb2.x, xb2.y); bl1.x = packlo2(xb2.x, xb2.y, bh1.x);
        bh1.y = packh2(xb3.x, xb3.y); bl1.y = packlo2(xb3.x, xb3.y, bh1.y);
        *(uint2*)(st + QST_BH + ftr * 256 + fl * 8) = bh0;
        *(uint2*)(st + QST_BL + ftr * 256 + fl * 8) = bl0;
        *(uint2*)(st + QST_BH + (ftr + 8) * 256 + fl * 8) = bh1;
        *(uint2*)(st + QST_BL + (ftr + 8) * 256 + fl * 8) = bl1;
    }
    __syncthreads();

    #pragma unroll 1
    for (int it = 0; it < 16; it++) {
        if (it + 1 < 16) {
            int ko = (it + 1) * 16;
            xa0 = vlo ? *(const float2*)(Ap_ll + ko)     : Z2;
            xa1 = vhi ? *(const float2*)(Ap_hl + ko)     : Z2;
            xa2 = vlo ? *(const float2*)(Ap_ll + ko + 8) : Z2;
            xa3 = vhi ? *(const float2*)(Ap_hl + ko + 8) : Z2;
            xb0 = *(const float2*)(Wp0 + ko);
            xb1 = *(const float2*)(Wp0 + ko + 8);
            xb2 = *(const float2*)(Wp1 + ko);
            xb3 = *(const float2*)(Wp1 + ko + 8);
        }

        {
            const unsigned char* st = sm[it & 1];
            uint4 ah[2];
            #pragma unroll
            for (int mt = 0; mt < 2; mt++) {
                int tr = (wm >> 4) + mt;
                ah[mt] = *(const uint4*)(st + QST_AH + tr * 512 + lane * 16);
            }
            #pragma unroll
            for (int nt = 0; nt < 8; nt++) {
                int tn = (wn >> 3) + nt;
                uint2 bh = *(const uint2*)(st + QST_BH + tn * 256 + lane * 8);
                uint2 bl = *(const uint2*)(st + QST_BL + tn * 256 + lane * 8);
                MMA_F16(acc[0][nt], ah[0], bl.x, bl.y);
                MMA_F16(acc[1][nt], ah[1], bl.x, bl.y);
                MMA_F16(acc[0][nt], ah[0], bh.x, bh.y);
                MMA_F16(acc[1][nt], ah[1], bh.x, bh.y);
            }
        }

        if (it + 1 < 16) {
            unsigned char* st = sm[(it + 1) & 1];
            uint4 h;
            h.x = packh2(xa0.x, xa0.y);
            h.y = packh2(xa1.x, xa1.y);
            h.z = packh2(xa2.x, xa2.y);
            h.w = packh2(xa3.x, xa3.y);
            *(uint4*)(st + QST_AH + ftr * 512 + fl * 16) = h;
            uint2 bh0, bl0, bh1, bl1;
            bh0.x = packh2(xb0.x, xb0.y); bl0.x = packlo2(xb0.x, xb0.y, bh0.x);
            bh0.y = packh2(xb1.x, xb1.y); bl0.y = packlo2(xb1.x, xb1.y, bh0.y);
            bh1.x = packh2(xb2.x, xb2.y); bl1.x = packlo2(xb2.x, xb2.y, bh1.x);
            bh1.y = packh2(xb3.x, xb3.y); bl1.y = packlo2(xb3.x, xb3.y, bh1.y);
            *(uint2*)(st + QST_BH + ftr * 256 + fl * 8) = bh0;
            *(uint2*)(st + QST_BL + ftr * 256 + fl * 8) = bl0;
            *(uint2*)(st + QST_BH + (ftr + 8) * 256 + fl * 8) = bh1;
            *(uint2*)(st + QST_BL + (ftr + 8) * 256 + fl * 8) = bl1;
        }
        __syncthreads();
    }

    // fp16 permuted epilogue
    #pragma unroll
    for (int mt = 0; mt < 2; mt++) {
        int r0 = m0 + wm + mt * 16 + g;
        #pragma unroll
        for (int nt = 0; nt < 8; nt++) {
            int jl = wn + nt * 8 + 2 * tig;
            float bx = bias[n0 + (jl >> 1)];
            float by = bias[n0 + 64 + (jl >> 1)];
            if (r0 < M) {
                *(__half2*)(H + (size_t)r0 * HIDDEN + n0 + jl) =
                    __halves2half2(__float2half_rn((acc[mt][nt][0] + bx) * scale),
                                   __float2half_rn((acc[mt][nt][1] + by) * scale));
            }
            if (r0 + 8 < M) {
                *(__half2*)(H + (size_t)(r0 + 8) * HIDDEN + n0 + jl) =
                    __halves2half2(__float2half_rn((acc[mt][nt][2] + bx) * scale),
                                   __float2half_rn((acc[mt][nt][3] + by) * scale));
            }
        }
    }
}

// ================ O-proj GEMM: fp16 permuted A (exact), split B, 2-term ======
#define ST_AH 0
#define ST_AL 4096
#define ST_BH 8192
#define ST_BL 12288
#define ST_SZ 16384

__global__ void __launch_bounds__(256, 2) gemm_oproj_kernel(
    const __half* __restrict__ AH,
    const float* __restrict__ W, const float* __restrict__ bias,
    float* __restrict__ C, int M)
{
    __shared__ __align__(16) unsigned char sm[2][ST_SZ];

    const int tid  = threadIdx.x;
    const int lane = tid & 31;
    const int warp = tid >> 5;
    const int g    = lane >> 2;
    const int tig  = lane & 3;
    const int wm   = (warp >> 1) * 32;
    const int wn   = (warp & 1) * 64;

    const int m0 = blockIdx.x * 128;
    const int n0 = blockIdx.y * 128;

    const int ftr = tid >> 5;
    const int fl  = lane;
    const int arow_lo = m0 + ftr * 16 + g;
    const int arow_hi = arow_lo + 8;
    const bool vlo = arow_lo < M, vhi = arow_hi < M;
    const uint32_t* Aw_lo = (const uint32_t*)(AH + (size_t)arow_lo * HIDDEN);
    const uint32_t* Aw_hi = (const uint32_t*)(AH + (size_t)arow_hi * HIDDEN);

    const int wr0 = n0 + ftr * 8 + g;
    const int wr1 = n0 + (ftr + 8) * 8 + g;
    const float* Wr0 = W + (size_t)wr0 * HIDDEN;
    const float* Wr1 = W + (size_t)wr1 * HIDDEN;

    uint32_t xa0, xa1, xa2, xa3;
    float2 xb0, xb1, xb2, xb3;

    #define WPAIR(Wr, w) make_float2(Wr[(w) + (((w) >= 64) ? 64 : 0)],           \
                                     Wr[(w) + (((w) >= 64) ? 64 : 0) + 64])

    {
        int w0 = tig, w1 = tig + 4;
        xa0 = vlo ? Aw_lo[w0] : 0u;
        xa1 = vhi ? Aw_hi[w0] : 0u;
        xa2 = vlo ? Aw_lo[w1] : 0u;
        xa3 = vhi ? Aw_hi[w1] : 0u;
        xb0 = WPAIR(Wr0, w0); xb1 = WPAIR(Wr0, w1);
        xb2 = WPAIR(Wr1, w0); xb3 = WPAIR(Wr1, w1);
    }

    float acc[2][8][4];
    #pragma unroll
    for (int mt = 0; mt < 2; mt++)
        #pragma unroll
        for (int nt = 0; nt < 8; nt++)
            #pragma unroll
            for (int r = 0; r < 4; r++) acc[mt][nt][r] = 0.f;

    {
        unsigned char* st = sm[0];
        *(uint4*)(st + ST_AH + ftr * 512 + fl * 16) = make_uint4(xa0, xa1, xa2, xa3);
        uint2 bh0, bl0, bh1, bl1;
        bh0.x = packh2(xb0.x, xb0.y); bl0.x = packlo2(xb0.x, xb0.y, bh0.x);
        bh0.y = packh2(xb1.x, xb1.y); bl0.y = packlo2(xb1.x, xb1.y, bh0.y);
        bh1.x = packh2(xb2.x, xb2.y); bl1.x = packlo2(xb2.x, xb2.y, bh1.x);
        bh1.y = packh2(xb3.x, xb3.y); bl1.y = packlo2(xb3.x, xb3.y, bh1.y);
        *(uint2*)(st + ST_BH + ftr * 256 + fl * 8) = bh0;
        *(uint2*)(st + ST_BL + ftr * 256 + fl * 8) = bl0;
        *(uint2*)(st + ST_BH + (ftr + 8) * 256 + fl * 8) = bh1;
        *(uint2*)(st + ST_BL + (ftr + 8) * 256 + fl * 8) = bl1;
    }
    __syncthreads();

    #pragma unroll 1
    for (int it = 0; it < 16; it++) {
        if (it + 1 < 16) {
            int w0 = (it + 1) * 8 + tig, w1 = w0 + 4;
            xa0 = vlo ? Aw_lo[w0] : 0u;
            xa1 = vhi ? Aw_hi[w0] : 0u;
            xa2 = vlo ? Aw_lo[w1] : 0u;
            xa3 = vhi ? Aw_hi[w1] : 0u;
            xb0 = WPAIR(Wr0, w0); xb1 = WPAIR(Wr0, w1);
            xb2 = WPAIR(Wr1, w0); xb3 = WPAIR(Wr1, w1);
        }

        {
            const unsigned char* st = sm[it & 1];
            uint4 ah[2];
            #pragma unroll
            for (int mt = 0; mt < 2; mt++) {
                int tr = (wm >> 4) + mt;
                ah[mt] = *(const uint4*)(st + ST_AH + tr * 512 + lane * 16);
            }
            #pragma unroll
            for (int nt = 0; nt < 8; nt++) {
                int tn = (wn >> 3) + nt;
                uint2 bh = *(const uint2*)(st + ST_BH + tn * 256 + lane * 8);
                uint2 bl = *(const uint2*)(st + ST_BL + tn * 256 + lane * 8);
                MMA_F16(acc[0][nt], ah[0], bl.x, bl.y);
                MMA_F16(acc[1][nt], ah[1], bl.x, bl.y);
                MMA_F16(acc[0][nt], ah[0], bh.x, bh.y);
                MMA_F16(acc[1][nt], ah[1], bh.x, bh.y);
            }
        }

        if (it + 1 < 16) {
            unsigned char* st = sm[(it + 1) & 1];
            *(uint4*)(st + ST_AH + ftr * 512 + fl * 16) = make_uint4(xa0, xa1, xa2, xa3);
            uint2 bh0, bl0, bh1, bl1;
            bh0.x = packh2(xb0.x, xb0.y); bl0.x = packlo2(xb0.x, xb0.y, bh0.x);
            bh0.y = packh2(xb1.x, xb1.y); bl0.y = packlo2(xb1.x, xb1.y, bh0.y);
            bh1.x = packh2(xb2.x, xb2.y); bl1.x = packlo2(xb2.x, xb2.y, bh1.x);
            bh1.y = packh2(xb3.x, xb3.y); bl1.y = packlo2(xb3.x, xb3.y, bh1.y);
            *(uint2*)(st + ST_BH + ftr * 256 + fl * 8) = bh0;
            *(uint2*)(st + ST_BL + ftr * 256 + fl * 8) = bl0;
            *(uint2*)(st + ST_BH + (ftr + 8) * 256 + fl * 8) = bh1;
            *(uint2*)(st + ST_BL + (ftr + 8) * 256 + fl * 8) = bl1;
        }
        __syncthreads();
    }
    #undef WPAIR

    // fp32 epilogue
    #pragma unroll
    for (int mt = 0; mt < 2; mt++) {
        int r0 = m0 + wm + mt * 16 + g;
        #pragma unroll
        for (int nt = 0; nt < 8; nt++) {
            int c = n0 + wn + nt * 8 + 2 * tig;
            float bx = bias[c], by = bias[c + 1];
            if (r0 < M) {
                float2 o0;
                o0.x = acc[mt][nt][0] + bx;
                o0.y = acc[mt][nt][1] + by;
                *(float2*)(C + (size_t)r0 * HIDDEN + c) = o0;
            }
            if (r0 + 8 < M) {
                float2 o1;
                o1.x = acc[mt][nt][2] + bx;
                o1.y = acc[mt][nt][3] + by;
                *(float2*)(C + (size_t)(r0 + 8) * HIDDEN + c) = o1;
            }
        }
    }
}

// ---------------- attention: one warp per node, all-fp16, 8-edge unroll -----
__global__ void __launch_bounds__(256) attn_kernel(int n) {
    int gw   = (blockIdx.x * blockDim.x + threadIdx.x) >> 5;
    int lane = threadIdx.x & 31;
    if (gw >= n) return;
    const int i = gw;
    const int start = g_offs[i];
    const int end   = g_offs[i + 1];

    const __half2* QB = (const __half2*)g_qh;
    const __half2* KB = (const __half2*)g_kh;
    const __half2* VB = (const __half2*)g_vh;

    float2 ql[4];
    #pragma unroll
    for (int c = 0; c < 4; c++)
        ql[c] = __half22float2(QB[(size_t)i * 128 + c * 32 + lane]);

    float m = __int_as_float(0xff800000);
    float d = 0.f;
    float2 acc[4] = {};

    int p = start;
    for (; p + 7 < end; p += 8) {
        int cn[8];
        #pragma unroll
        for (int e = 0; e < 8; e++) cn[e] = g_ccol[p + e];

        float s[8] = {0.f, 0.f, 0.f, 0.f, 0.f, 0.f, 0.f, 0.f};
        #pragma unroll
        for (int c = 0; c < 4; c++) {
            int o = c * 32 + lane;
            #pragma unroll
            for (int e = 0; e < 8; e++) {
                float2 kf = __half22float2(__ldg(KB + (size_t)cn[e] * 128 + o));
                s[e] += ql[c].x * kf.x + ql[c].y * kf.y;
            }
        }
        #pragma unroll
        for (int e = 0; e < 8; e++) {
            s[e] += __shfl_xor_sync(0xffffffffu, s[e], 16);
            s[e] += __shfl_xor_sync(0xffffffffu, s[e], 8);
        }

        float m2 = m;
        #pragma unroll
        for (int e = 0; e < 8; e++) m2 = fmaxf(m2, s[e]);
        float cf = __expf(m - m2);
        float w[8], sw = 0.f;
        #pragma unroll
        for (int e = 0; e < 8; e++) { w[e] = __expf(s[e] - m2); sw += w[e]; }
        d = d * cf + sw;
        m = m2;

        #pragma unroll
        for (int c = 0; c < 4; c++) {
            int o = c * 32 + lane;
            float tx = acc[c].x * cf, ty = acc[c].y * cf;
            #pragma unroll
            for (int e = 0; e < 8; e++) {
                float2 vf = __half22float2(__ldg(VB + (size_t)cn[e] * 128 + o));
                tx += w[e] * vf.x;
                ty += w[e] * vf.y;
            }
            acc[c].x = tx; acc[c].y = ty;
        }
    }
    for (; p < end; p++) {
        int c0 = g_ccol[p];
        float s0 = 0.f;
        #pragma unroll
        for (int c = 0; c < 4; c++) {
            float2 kf = __half22float2(__ldg(KB + (size_t)c0 * 128 + c * 32 + lane));
            s0 += ql[c].x * kf.x + ql[c].y * kf.y;
        }
        s0 += __shfl_xor_sync(0xffffffffu, s0, 16);
        s0 += __shfl_xor_sync(0xffffffffu, s0, 8);
        float m2 = fmaxf(m, s0);
        float cf = __expf(m - m2);
        float w0 = __expf(s0 - m2);
        d = d * cf + w0;
        m = m2;
        #pragma unroll
        for (int c = 0; c < 4; c++) {
            float2 vf = __half22float2(__ldg(VB + (size_t)c0 * 128 + c * 32 + lane));
            acc[c].x = acc[c].x * cf + w0 * vf.x;
            acc[c].y = acc[c].y * cf + w0 * vf.y;
        }
    }

    float rd = (end > start) ? 1.f / d : 0.f;
    __half2* AO = (__half2*)g_aoh;
    #pragma unroll
    for (int c = 0; c < 4; c++) {
        AO[(size_t)i * 128 + c * 32 + lane] =
            __halves2half2(__float2half_rn(acc[c].x * rd),
                           __float2half_rn(acc[c].y * rd));
    }
}

// ---------------- launch ----------------
extern "C" void kernel_launch(void* const* d_in, const int* in_sizes, int n_in,
                              void* d_out, int out_size) {
    const float* h   = (const float*)d_in[0];
    const int*   row = (const int*)d_in[1];
    const int*   col = (const int*)d_in[2];
    const float* Wq  = (const float*)d_in[3];
    const float* bq  = (const float*)d_in[4];
    const float* Wk  = (const float*)d_in[5];
    const float* bk  = (const float*)d_in[6];
    const float* Wv  = (const float*)d_in[7];
    const float* bv  = (const float*)d_in[8];
    const float* Wo  = (const float*)d_in[9];
    const float* bo  = (const float*)d_in[10];
    float* out = (float*)d_out;

    const int N = in_sizes[0] / HIDDEN;
    const int E = in_sizes[1];

    __half *pqh, *pkh, *pvh, *paoh;
    int *pdeg;
    cudaGetSymbolAddress((void**)&pqh, g_qh);
    cudaGetSymbolAddress((void**)&pkh, g_kh);
    cudaGetSymbolAddress((void**)&pvh, g_vh);
    cudaGetSymbolAddress((void**)&paoh, g_aoh);
    cudaGetSymbolAddress((void**)&pdeg, g_deg);

    static cudaStream_t s2 = nullptr;
    static cudaEvent_t evFork = nullptr, evJoin = nullptr;
    if (!s2) {
        cudaStreamCreateWithFlags(&s2, cudaStreamNonBlocking);
        cudaEventCreateWithFlags(&evFork, cudaEventDisableTiming);
        cudaEventCreateWithFlags(&evJoin, cudaEventDisableTiming);
    }

    // fork: CSR build on s2, QKV GEMM on main stream
    cudaEventRecord(evFork, 0);
    cudaStreamWaitEvent(s2, evFork, 0);
    cudaMemsetAsync(pdeg, 0, (size_t)N * sizeof(int), s2);
    count_deg_kernel<<<(E + 255) / 256, 256, 0, s2>>>(row, E);
    scan_kernel<<<1, 1024, 0, s2>>>(N);
    scatter_kernel<<<(E + 255) / 256, 256, 0, s2>>>(row, col, E);
    cudaEventRecord(evJoin, s2);

    const float scaling = 0.17677669529663687f;  // 32^-0.5
    dim3 gqkv((N + 127) / 128, HIDDEN / 128, 3);
    gemm_qkv_kernel<<<gqkv, 256>>>(h, Wq, Wk, Wv, bq, bk, bv,
                                   pqh, pkh, pvh, N, scaling);

    cudaStreamWaitEvent(0, evJoin, 0);
    attn_kernel<<<(N + 7) / 8, 256>>>(N);

    dim3 go((N + 127) / 128, HIDDEN / 128, 1);
    gemm_oproj_kernel<<<go, 256>>>(paoh, Wo, bo, out, N);
}

// round 13
// speedup vs baseline: 1.2599x; 1.0723x over previous
#include <cuda_runtime.h>
#include <cuda_fp16.h>
#include <cstdint>

#define HIDDEN 256
#define HEADS 8
#define MAXN 50000
#define MAXE 800000

// ---------------- scratch ----------------
// Permuted fp16 layout (per row of 256 halfs): half idx p, block n0=(p&128):
//   jj = p & 127; feat = n0 + (jj&1)*64 + (jj>>1)
// => word w: w<64 -> feats (w, w+64); w>=64 -> feats (w+64, w+128).
//   Both feats of a word share head (w%8); lane l reads words c*32+l -> head l%8.
__device__ __half g_qh[(size_t)MAXN * HIDDEN];
__device__ __half g_kh[(size_t)MAXN * HIDDEN];
__device__ __half g_vh[(size_t)MAXN * HIDDEN];
__device__ __half g_aoh[(size_t)MAXN * HIDDEN];
__device__ int    g_deg[MAXN];
__device__ int    g_offs[MAXN + 1];
__device__ int    g_cursor[MAXN];
__device__ int    g_ccol[MAXE];

// ---------------- CSR build ----------------
__global__ void count_deg_kernel(const int* __restrict__ row, int e) {
    int i = blockIdx.x * blockDim.x + threadIdx.x;
    if (i < e) atomicAdd(&g_deg[row[i]], 1);
}

__global__ void scan_kernel(int n) {
    __shared__ int wsum[32];
    int lane = threadIdx.x & 31;
    int wid  = threadIdx.x >> 5;
    int carry = 0;
    for (int base = 0; base < n; base += 1024) {
        int i = base + (int)threadIdx.x;
        int v = (i < n) ? g_deg[i] : 0;
        int x = v;
        #pragma unroll
        for (int d = 1; d < 32; d <<= 1) {
            int y = __shfl_up_sync(0xffffffffu, x, d);
            if (lane >= d) x += y;
        }
        if (lane == 31) wsum[wid] = x;
        __syncthreads();
        if (wid == 0) {
            int wv = wsum[lane];
            #pragma unroll
            for (int d = 1; d < 32; d <<= 1) {
                int y = __shfl_up_sync(0xffffffffu, wv, d);
                if (lane >= d) wv += y;
            }
            wsum[lane] = wv;
        }
        __syncthreads();
        int inc = x + (wid > 0 ? wsum[wid - 1] : 0) + carry;
        if (i < n) {
            int excl = inc - v;
            g_offs[i]   = excl;
            g_cursor[i] = excl;
        }
        carry += wsum[31];
        __syncthreads();
    }
    if (threadIdx.x == 0) g_offs[n] = carry;
}

__global__ void scatter_kernel(const int* __restrict__ row, const int* __restrict__ col, int e) {
    int i = blockIdx.x * blockDim.x + threadIdx.x;
    if (i < e) {
        int slot = atomicAdd(&g_cursor[row[i]], 1);
        g_ccol[slot] = col[i];
    }
}

// ================ shared GEMM pieces ================
__device__ __forceinline__ uint32_t packh2(float x, float y) {
    __half2 h = __halves2half2(__float2half_rn(x), __float2half_rn(y));
    return *(uint32_t*)&h;
}
__device__ __forceinline__ uint32_t packlo2(float x, float y, uint32_t h) {
    __half2 hh = *(__half2*)&h;
    float rx = x - __half2float(__low2half(hh));
    float ry = y - __half2float(__high2half(hh));
    return packh2(rx, ry);
}

#define MMA_F16(ACC, AV, B0, B1)                                           \
    asm volatile(                                                          \
        "mma.sync.aligned.m16n8k16.row.col.f32.f16.f16.f32 "              \
        "{%0,%1,%2,%3}, {%4,%5,%6,%7}, {%8,%9}, {%0,%1,%2,%3};"           \
        : "+f"(ACC[0]), "+f"(ACC[1]), "+f"(ACC[2]), "+f"(ACC[3])          \
        : "r"(AV.x), "r"(AV.y), "r"(AV.z), "r"(AV.w),                     \
          "r"(B0), "r"(B1))

// ================ QKV GEMM: pure fp16 (1-term), permuted fp16 out ===========
// BM=128 BN=128 BK=16, 8 warps, warp tile 32x64. Both operand-lo terms are
// below the fp16 output quantization floor (measured +0.5e-4 for A-drop).
#define QST_AH 0
#define QST_BH 4096
#define QST_SZ 8192

__global__ void __launch_bounds__(256, 2) gemm_qkv_kernel(
    const float* __restrict__ A,
    const float* __restrict__ W0, const float* __restrict__ W1, const float* __restrict__ W2,
    const float* __restrict__ b0_, const float* __restrict__ b1_, const float* __restrict__ b2_,
    __half* __restrict__ QH, __half* __restrict__ KH, __half* __restrict__ VH,
    int M, float scale0)
{
    __shared__ __align__(16) unsigned char sm[2][QST_SZ];

    const int z = blockIdx.z;
    const float* W    = (z == 0) ? W0 : (z == 1) ? W1 : W2;
    const float* bias = (z == 0) ? b0_ : (z == 1) ? b1_ : b2_;
    __half* H         = (z == 0) ? QH : (z == 1) ? KH : VH;
    const float scale = (z == 0) ? scale0 : 1.f;

    const int tid  = threadIdx.x;
    const int lane = tid & 31;
    const int warp = tid >> 5;
    const int g    = lane >> 2;
    const int tig  = lane & 3;
    const int wm   = (warp >> 1) * 32;
    const int wn   = (warp & 1) * 64;

    const int m0 = blockIdx.x * 128;
    const int n0 = blockIdx.y * 128;

    const int ftr = tid >> 5;
    const int fl  = lane;
    const int arow_lo = m0 + ftr * 16 + g;
    const int arow_hi = arow_lo + 8;
    const bool vlo = arow_lo < M, vhi = arow_hi < M;
    const float* Ap_ll = A + (size_t)arow_lo * HIDDEN + 2 * tig;
    const float* Ap_hl = A + (size_t)arow_hi * HIDDEN + 2 * tig;

    // permuted W rows so the fp16 epilogue is contiguous
    const int jl0 = ftr * 8 + g;
    const int jl1 = (ftr + 8) * 8 + g;
    const int wr0 = n0 + ((jl0 & 1) << 6) + (jl0 >> 1);
    const int wr1 = n0 + ((jl1 & 1) << 6) + (jl1 >> 1);
    const float* Wp0 = W + (size_t)wr0 * HIDDEN + 2 * tig;
    const float* Wp1 = W + (size_t)wr1 * HIDDEN + 2 * tig;

    float2 xa0, xa1, xa2, xa3, xb0, xb1, xb2, xb3;
    const float2 Z2 = make_float2(0.f, 0.f);

    xa0 = vlo ? *(const float2*)(Ap_ll)     : Z2;
    xa1 = vhi ? *(const float2*)(Ap_hl)     : Z2;
    xa2 = vlo ? *(const float2*)(Ap_ll + 8) : Z2;
    xa3 = vhi ? *(const float2*)(Ap_hl + 8) : Z2;
    xb0 = *(const float2*)(Wp0);
    xb1 = *(const float2*)(Wp0 + 8);
    xb2 = *(const float2*)(Wp1);
    xb3 = *(const float2*)(Wp1 + 8);

    float acc[2][8][4];
    #pragma unroll
    for (int mt = 0; mt < 2; mt++)
        #pragma unroll
        for (int nt = 0; nt < 8; nt++)
            #pragma unroll
            for (int r = 0; r < 4; r++) acc[mt][nt][r] = 0.f;

    {
        unsigned char* st = sm[0];
        uint4 h;
        h.x = packh2(xa0.x, xa0.y);
        h.y = packh2(xa1.x, xa1.y);
        h.z = packh2(xa2.x, xa2.y);
        h.w = packh2(xa3.x, xa3.y);
        *(uint4*)(st + QST_AH + ftr * 512 + fl * 16) = h;
        uint2 bh0, bh1;
        bh0.x = packh2(xb0.x, xb0.y);
        bh0.y = packh2(xb1.x, xb1.y);
        bh1.x = packh2(xb2.x, xb2.y);
        bh1.y = packh2(xb3.x, xb3.y);
        *(uint2*)(st + QST_BH + ftr * 256 + fl * 8) = bh0;
        *(uint2*)(st + QST_BH + (ftr + 8) * 256 + fl * 8) = bh1;
    }
    __syncthreads();

    #pragma unroll 1
    for (int it = 0; it < 16; it++) {
        if (it + 1 < 16) {
            int ko = (it + 1) * 16;
            xa0 = vlo ? *(const float2*)(Ap_ll + ko)     : Z2;
            xa1 = vhi ? *(const float2*)(Ap_hl + ko)     : Z2;
            xa2 = vlo ? *(const float2*)(Ap_ll + ko + 8) : Z2;
            xa3 = vhi ? *(const float2*)(Ap_hl + ko + 8) : Z2;
            xb0 = *(const float2*)(Wp0 + ko);
            xb1 = *(const float2*)(Wp0 + ko + 8);
            xb2 = *(const float2*)(Wp1 + ko);
            xb3 = *(const float2*)(Wp1 + ko + 8);
        }

        {
            const unsigned char* st = sm[it & 1];
            uint4 ah[2];
            #pragma unroll
            for (int mt = 0; mt < 2; mt++) {
                int tr = (wm >> 4) + mt;
                ah[mt] = *(const uint4*)(st + QST_AH + tr * 512 + lane * 16);
            }
            #pragma unroll
            for (int nt = 0; nt < 8; nt++) {
                int tn = (wn >> 3) + nt;
                uint2 bh = *(const uint2*)(st + QST_BH + tn * 256 + lane * 8);
                MMA_F16(acc[0][nt], ah[0], bh.x, bh.y);
                MMA_F16(acc[1][nt], ah[1], bh.x, bh.y);
            }
        }

        if (it + 1 < 16) {
            unsigned char* st = sm[(it + 1) & 1];
            uint4 h;
            h.x = packh2(xa0.x, xa0.y);
            h.y = packh2(xa1.x, xa1.y);
            h.z = packh2(xa2.x, xa2.y);
            h.w = packh2(xa3.x, xa3.y);
            *(uint4*)(st + QST_AH + ftr * 512 + fl * 16) = h;
            uint2 bh0, bh1;
            bh0.x = packh2(xb0.x, xb0.y);
            bh0.y = packh2(xb1.x, xb1.y);
            bh1.x = packh2(xb2.x, xb2.y);
            bh1.y = packh2(xb3.x, xb3.y);
            *(uint2*)(st + QST_BH + ftr * 256 + fl * 8) = bh0;
            *(uint2*)(st + QST_BH + (ftr + 8) * 256 + fl * 8) = bh1;
        }
        __syncthreads();
    }

    // fp16 permuted epilogue
    #pragma unroll
    for (int mt = 0; mt < 2; mt++) {
        int r0 = m0 + wm + mt * 16 + g;
        #pragma unroll
        for (int nt = 0; nt < 8; nt++) {
            int jl = wn + nt * 8 + 2 * tig;
            float bx = bias[n0 + (jl >> 1)];
            float by = bias[n0 + 64 + (jl >> 1)];
            if (r0 < M) {
                *(__half2*)(H + (size_t)r0 * HIDDEN + n0 + jl) =
                    __halves2half2(__float2half_rn((acc[mt][nt][0] + bx) * scale),
                                   __float2half_rn((acc[mt][nt][1] + by) * scale));
            }
            if (r0 + 8 < M) {
                *(__half2*)(H + (size_t)(r0 + 8) * HIDDEN + n0 + jl) =
                    __halves2half2(__float2half_rn((acc[mt][nt][2] + bx) * scale),
                                   __float2half_rn((acc[mt][nt][3] + by) * scale));
            }
        }
    }
}

// ================ O-proj GEMM: fp16 permuted A (exact), split B, 2-term ======
#define ST_AH 0
#define ST_AL 4096
#define ST_BH 8192
#define ST_BL 12288
#define ST_SZ 16384

__global__ void __launch_bounds__(256, 2) gemm_oproj_kernel(
    const __half* __restrict__ AH,
    const float* __restrict__ W, const float* __restrict__ bias,
    float* __restrict__ C, int M)
{
    __shared__ __align__(16) unsigned char sm[2][ST_SZ];

    const int tid  = threadIdx.x;
    const int lane = tid & 31;
    const int warp = tid >> 5;
    const int g    = lane >> 2;
    const int tig  = lane & 3;
    const int wm   = (warp >> 1) * 32;
    const int wn   = (warp & 1) * 64;

    const int m0 = blockIdx.x * 128;
    const int n0 = blockIdx.y * 128;

    const int ftr = tid >> 5;
    const int fl  = lane;
    const int arow_lo = m0 + ftr * 16 + g;
    const int arow_hi = arow_lo + 8;
    const bool vlo = arow_lo < M, vhi = arow_hi < M;
    const uint32_t* Aw_lo = (const uint32_t*)(AH + (size_t)arow_lo * HIDDEN);
    const uint32_t* Aw_hi = (const uint32_t*)(AH + (size_t)arow_hi * HIDDEN);

    const int wr0 = n0 + ftr * 8 + g;
    const int wr1 = n0 + (ftr + 8) * 8 + g;
    const float* Wr0 = W + (size_t)wr0 * HIDDEN;
    const float* Wr1 = W + (size_t)wr1 * HIDDEN;

    uint32_t xa0, xa1, xa2, xa3;
    float2 xb0, xb1, xb2, xb3;

    #define WPAIR(Wr, w) make_float2(Wr[(w) + (((w) >= 64) ? 64 : 0)],           \
                                     Wr[(w) + (((w) >= 64) ? 64 : 0) + 64])

    {
        int w0 = tig, w1 = tig + 4;
        xa0 = vlo ? Aw_lo[w0] : 0u;
        xa1 = vhi ? Aw_hi[w0] : 0u;
        xa2 = vlo ? Aw_lo[w1] : 0u;
        xa3 = vhi ? Aw_hi[w1] : 0u;
        xb0 = WPAIR(Wr0, w0); xb1 = WPAIR(Wr0, w1);
        xb2 = WPAIR(Wr1, w0); xb3 = WPAIR(Wr1, w1);
    }

    float acc[2][8][4];
    #pragma unroll
    for (int mt = 0; mt < 2; mt++)
        #pragma unroll
        for (int nt = 0; nt < 8; nt++)
            #pragma unroll
            for (int r = 0; r < 4; r++) acc[mt][nt][r] = 0.f;

    {
        unsigned char* st = sm[0];
        *(uint4*)(st + ST_AH + ftr * 512 + fl * 16) = make_uint4(xa0, xa1, xa2, xa3);
        uint2 bh0, bl0, bh1, bl1;
        bh0.x = packh2(xb0.x, xb0.y); bl0.x = packlo2(xb0.x, xb0.y, bh0.x);
        bh0.y = packh2(xb1.x, xb1.y); bl0.y = packlo2(xb1.x, xb1.y, bh0.y);
        bh1.x = packh2(xb2.x, xb2.y); bl1.x = packlo2(xb2.x, xb2.y, bh1.x);
        bh1.y = packh2(xb3.x, xb3.y); bl1.y = packlo2(xb3.x, xb3.y, bh1.y);
        *(uint2*)(st + ST_BH + ftr * 256 + fl * 8) = bh0;
        *(uint2*)(st + ST_BL + ftr * 256 + fl * 8) = bl0;
        *(uint2*)(st + ST_BH + (ftr + 8) * 256 + fl * 8) = bh1;
        *(uint2*)(st + ST_BL + (ftr + 8) * 256 + fl * 8) = bl1;
    }
    __syncthreads();

    #pragma unroll 1
    for (int it = 0; it < 16; it++) {
        if (it + 1 < 16) {
            int w0 = (it + 1) * 8 + tig, w1 = w0 + 4;
            xa0 = vlo ? Aw_lo[w0] : 0u;
            xa1 = vhi ? Aw_hi[w0] : 0u;
            xa2 = vlo ? Aw_lo[w1] : 0u;
            xa3 = vhi ? Aw_hi[w1] : 0u;
            xb0 = WPAIR(Wr0, w0); xb1 = WPAIR(Wr0, w1);
            xb2 = WPAIR(Wr1, w0); xb3 = WPAIR(Wr1, w1);
        }

        {
            const unsigned char* st = sm[it & 1];
            uint4 ah[2];
            #pragma unroll
            for (int mt = 0; mt < 2; mt++) {
                int tr = (wm >> 4) + mt;
                ah[mt] = *(const uint4*)(st + ST_AH + tr * 512 + lane * 16);
            }
            #pragma unroll
            for (int nt = 0; nt < 8; nt++) {
                int tn = (wn >> 3) + nt;
                uint2 bh = *(const uint2*)(st + ST_BH + tn * 256 + lane * 8);
                uint2 bl = *(const uint2*)(st + ST_BL + tn * 256 + lane * 8);
                MMA_F16(acc[0][nt], ah[0], bl.x, bl.y);
                MMA_F16(acc[1][nt], ah[1], bl.x, bl.y);
                MMA_F16(acc[0][nt], ah[0], bh.x, bh.y);
                MMA_F16(acc[1][nt], ah[1], bh.x, bh.y);
            }
        }

        if (it + 1 < 16) {
            unsigned char* st = sm[(it + 1) & 1];
            *(uint4*)(st + ST_AH + ftr * 512 + fl * 16) = make_uint4(xa0, xa1, xa2, xa3);
            uint2 bh0, bl0, bh1, bl1;
            bh0.x = packh2(xb0.x, xb0.y); bl0.x = packlo2(xb0.x, xb0.y, bh0.x);
            bh0.y = packh2(xb1.x, xb1.y); bl0.y = packlo2(xb1.x, xb1.y, bh0.y);
            bh1.x = packh2(xb2.x, xb2.y); bl1.x = packlo2(xb2.x, xb2.y, bh1.x);
            bh1.y = packh2(xb3.x, xb3.y); bl1.y = packlo2(xb3.x, xb3.y, bh1.y);
            *(uint2*)(st + ST_BH + ftr * 256 + fl * 8) = bh0;
            *(uint2*)(st + ST_BL + ftr * 256 + fl * 8) = bl0;
            *(uint2*)(st + ST_BH + (ftr + 8) * 256 + fl * 8) = bh1;
            *(uint2*)(st + ST_BL + (ftr + 8) * 256 + fl * 8) = bl1;
        }
        __syncthreads();
    }
    #undef WPAIR

    // fp32 epilogue
    #pragma unroll
    for (int mt = 0; mt < 2; mt++) {
        int r0 = m0 + wm + mt * 16 + g;
        #pragma unroll
        for (int nt = 0; nt < 8; nt++) {
            int c = n0 + wn + nt * 8 + 2 * tig;
            float bx = bias[c], by = bias[c + 1];
            if (r0 < M) {
                float2 o0;
                o0.x = acc[mt][nt][0] + bx;
                o0.y = acc[mt][nt][1] + by;
                *(float2*)(C + (size_t)r0 * HIDDEN + c) = o0;
            }
            if (r0 + 8 < M) {
                float2 o1;
                o1.x = acc[mt][nt][2] + bx;
                o1.y = acc[mt][nt][3] + by;
                *(float2*)(C + (size_t)(r0 + 8) * HIDDEN + c) = o1;
            }
        }
    }
}

// ---------------- attention: one warp per node, all-fp16, 8-edge unroll -----
__global__ void __launch_bounds__(256) attn_kernel(int n) {
    int gw   = (blockIdx.x * blockDim.x + threadIdx.x) >> 5;
    int lane = threadIdx.x & 31;
    if (gw >= n) return;
    const int i = gw;
    const int start = g_offs[i];
    const int end   = g_offs[i + 1];

    const __half2* QB = (const __half2*)g_qh;
    const __half2* KB = (const __half2*)g_kh;
    const __half2* VB = (const __half2*)g_vh;

    float2 ql[4];
    #pragma unroll
    for (int c = 0; c < 4; c++)
        ql[c] = __half22float2(QB[(size_t)i * 128 + c * 32 + lane]);

    float m = __int_as_float(0xff800000);
    float d = 0.f;
    float2 acc[4] = {};

    int p = start;
    for (; p + 7 < end; p += 8) {
        int cn[8];
        #pragma unroll
        for (int e = 0; e < 8; e++) cn[e] = g_ccol[p + e];

        float s[8] = {0.f, 0.f, 0.f, 0.f, 0.f, 0.f, 0.f, 0.f};
        #pragma unroll
        for (int c = 0; c < 4; c++) {
            int o = c * 32 + lane;
            #pragma unroll
            for (int e = 0; e < 8; e++) {
                float2 kf = __half22float2(__ldg(KB + (size_t)cn[e] * 128 + o));
                s[e] += ql[c].x * kf.x + ql[c].y * kf.y;
            }
        }
        #pragma unroll
        for (int e = 0; e < 8; e++) {
            s[e] += __shfl_xor_sync(0xffffffffu, s[e], 16);
            s[e] += __shfl_xor_sync(0xffffffffu, s[e], 8);
        }

        float m2 = m;
        #pragma unroll
        for (int e = 0; e < 8; e++) m2 = fmaxf(m2, s[e]);
        float cf = __expf(m - m2);
        float w[8], sw = 0.f;
        #pragma unroll
        for (int e = 0; e < 8; e++) { w[e] = __expf(s[e] - m2); sw += w[e]; }
        d = d * cf + sw;
        m = m2;

        #pragma unroll
        for (int c = 0; c < 4; c++) {
            int o = c * 32 + lane;
            float tx = acc[c].x * cf, ty = acc[c].y * cf;
            #pragma unroll
            for (int e = 0; e < 8; e++) {
                float2 vf = __half22float2(__ldg(VB + (size_t)cn[e] * 128 + o));
                tx += w[e] * vf.x;
                ty += w[e] * vf.y;
            }
            acc[c].x = tx; acc[c].y = ty;
        }
    }
    for (; p < end; p++) {
        int c0 = g_ccol[p];
        float s0 = 0.f;
        #pragma unroll
        for (int c = 0; c < 4; c++) {
            float2 kf = __half22float2(__ldg(KB + (size_t)c0 * 128 + c * 32 + lane));
            s0 += ql[c].x * kf.x + ql[c].y * kf.y;
        }
        s0 += __shfl_xor_sync(0xffffffffu, s0, 16);
        s0 += __shfl_xor_sync(0xffffffffu, s0, 8);
        float m2 = fmaxf(m, s0);
        float cf = __expf(m - m2);
        float w0 = __expf(s0 - m2);
        d = d * cf + w0;
        m = m2;
        #pragma unroll
        for (int c = 0; c < 4; c++) {
            float2 vf = __half22float2(__ldg(VB + (size_t)c0 * 128 + c * 32 + lane));
            acc[c].x = acc[c].x * cf + w0 * vf.x;
            acc[c].y = acc[c].y * cf + w0 * vf.y;
        }
    }

    float rd = (end > start) ? 1.f / d : 0.f;
    __half2* AO = (__half2*)g_aoh;
    #pragma unroll
    for (int c = 0; c < 4; c++) {
        AO[(size_t)i * 128 + c * 32 + lane] =
            __halves2half2(__float2half_rn(acc[c].x * rd),
                           __float2half_rn(acc[c].y * rd));
    }
}

// ---------------- launch ----------------
extern "C" void kernel_launch(void* const* d_in, const int* in_sizes, int n_in,
                              void* d_out, int out_size) {
    const float* h   = (const float*)d_in[0];
    const int*   row = (const int*)d_in[1];
    const int*   col = (const int*)d_in[2];
    const float* Wq  = (const float*)d_in[3];
    const float* bq  = (const float*)d_in[4];
    const float* Wk  = (const float*)d_in[5];
    const float* bk  = (const float*)d_in[6];
    const float* Wv  = (const float*)d_in[7];
    const float* bv  = (const float*)d_in[8];
    const float* Wo  = (const float*)d_in[9];
    const float* bo  = (const float*)d_in[10];
    float* out = (float*)d_out;

    const int N = in_sizes[0] / HIDDEN;
    const int E = in_sizes[1];

    __half *pqh, *pkh, *pvh, *paoh;
    int *pdeg;
    cudaGetSymbolAddress((void**)&pqh, g_qh);
    cudaGetSymbolAddress((void**)&pkh, g_kh);
    cudaGetSymbolAddress((void**)&pvh, g_vh);
    cudaGetSymbolAddress((void**)&paoh, g_aoh);
    cudaGetSymbolAddress((void**)&pdeg, g_deg);

    static cudaStream_t s2 = nullptr;
    static cudaEvent_t evFork = nullptr, evJoin = nullptr;
    if (!s2) {
        cudaStreamCreateWithFlags(&s2, cudaStreamNonBlocking);
        cudaEventCreateWithFlags(&evFork, cudaEventDisableTiming);
        cudaEventCreateWithFlags(&evJoin, cudaEventDisableTiming);
    }

    // fork: CSR build on s2, QKV GEMM on main stream
    cudaEventRecord(evFork, 0);
    cudaStreamWaitEvent(s2, evFork, 0);
    cudaMemsetAsync(pdeg, 0, (size_t)N * sizeof(int), s2);
    count_deg_kernel<<<(E + 255) / 256, 256, 0, s2>>>(row, E);
    scan_kernel<<<1, 1024, 0, s2>>>(N);
    scatter_kernel<<<(E + 255) / 256, 256, 0, s2>>>(row, col, E);
    cudaEventRecord(evJoin, s2);

    const float scaling = 0.17677669529663687f;  // 32^-0.5
    dim3 gqkv((N + 127) / 128, HIDDEN / 128, 3);
    gemm_qkv_kernel<<<gqkv, 256>>>(h, Wq, Wk, Wv, bq, bk, bv,
                                   pqh, pkh, pvh, N, scaling);

    cudaStreamWaitEvent(0, evJoin, 0);
    attn_kernel<<<(N + 7) / 8, 256>>>(N);

    dim3 go((N + 127) / 128, HIDDEN / 128, 1);
    gemm_oproj_kernel<<<go, 256>>>(paoh, Wo, bo, out, N);
}

// round 14
// speedup vs baseline: 1.7356x; 1.3775x over previous
#include <cuda_runtime.h>
#include <cuda_fp16.h>
#include <cstdint>

#define HIDDEN 256
#define HEADS 8
#define MAXN 50000
#define MAXE 800000
#define NTILES_PAD 3136          // ceil(50000/16) padded past max CTA reach

// ---------------- scratch ----------------
// Permuted fp16 vector layout (per row of 256 halfs): half idx p, n0=(p&128):
//   jj = p & 127; feat = n0 + (jj&1)*64 + (jj>>1)
__device__ __half g_qh[(size_t)MAXN * HIDDEN];
__device__ __half g_kh[(size_t)MAXN * HIDDEN];
__device__ __half g_vh[(size_t)MAXN * HIDDEN];
__device__ __half g_aoh[(size_t)MAXN * HIDDEN];
// A in MMA-fragment order: cell c=(t*16+kc)*32+lane, 16B each
__device__ __half g_af[(size_t)NTILES_PAD * 16 * 32 * 8];
// W (q,k,v) fp16 fragment order w/ permuted rows: cell ((tn*16+kc)*32+lane), 8B
__device__ __half g_wf[3 * 32 * 16 * 32 * 4];
__device__ int    g_deg[MAXN];
__device__ int    g_offs[MAXN + 1];
__device__ int    g_cursor[MAXN];
__device__ int    g_ccol[MAXE];

// ---------------- CSR build ----------------
__global__ void count_deg_kernel(const int* __restrict__ row, int e) {
    int i = blockIdx.x * blockDim.x + threadIdx.x;
    if (i < e) atomicAdd(&g_deg[row[i]], 1);
}

__global__ void scan_kernel(int n) {
    __shared__ int wsum[32];
    int lane = threadIdx.x & 31;
    int wid  = threadIdx.x >> 5;
    int carry = 0;
    for (int base = 0; base < n; base += 1024) {
        int i = base + (int)threadIdx.x;
        int v = (i < n) ? g_deg[i] : 0;
        int x = v;
        #pragma unroll
        for (int d = 1; d < 32; d <<= 1) {
            int y = __shfl_up_sync(0xffffffffu, x, d);
            if (lane >= d) x += y;
        }
        if (lane == 31) wsum[wid] = x;
        __syncthreads();
        if (wid == 0) {
            int wv = wsum[lane];
            #pragma unroll
            for (int d = 1; d < 32; d <<= 1) {
                int y = __shfl_up_sync(0xffffffffu, wv, d);
                if (lane >= d) wv += y;
            }
            wsum[lane] = wv;
        }
        __syncthreads();
        int inc = x + (wid > 0 ? wsum[wid - 1] : 0) + carry;
        if (i < n) {
            int excl = inc - v;
            g_offs[i]   = excl;
            g_cursor[i] = excl;
        }
        carry += wsum[31];
        __syncthreads();
    }
    if (threadIdx.x == 0) g_offs[n] = carry;
}

__global__ void scatter_kernel(const int* __restrict__ row, const int* __restrict__ col, int e) {
    int i = blockIdx.x * blockDim.x + threadIdx.x;
    if (i < e) {
        int slot = atomicAdd(&g_cursor[row[i]], 1);
        g_ccol[slot] = col[i];
    }
}

// ---------------- helpers ----------------
__device__ __forceinline__ uint32_t packh2(float x, float y) {
    __half2 h = __halves2half2(__float2half_rn(x), __float2half_rn(y));
    return *(uint32_t*)&h;
}

#define MMA_F16(ACC, AV, B0, B1)                                           \
    asm volatile(                                                          \
        "mma.sync.aligned.m16n8k16.row.col.f32.f16.f16.f32 "              \
        "{%0,%1,%2,%3}, {%4,%5,%6,%7}, {%8,%9}, {%0,%1,%2,%3};"           \
        : "+f"(ACC[0]), "+f"(ACC[1]), "+f"(ACC[2]), "+f"(ACC[3])          \
        : "r"(AV.x), "r"(AV.y), "r"(AV.z), "r"(AV.w),                     \
          "r"(B0), "r"(B1))

#define CP_ASYNC16(dst, src)                                               \
    asm volatile("cp.async.ca.shared.global [%0], [%1], 16;"              \
                 :: "r"(dst), "l"(src))
#define CP_ASYNC8(dst, src)                                                \
    asm volatile("cp.async.ca.shared.global [%0], [%1], 8;"               \
                 :: "r"(dst), "l"(src))
#define CP_COMMIT()  asm volatile("cp.async.commit_group;" ::: "memory")
#define CP_WAIT2()   asm volatile("cp.async.wait_group 2;" ::: "memory")

// ---------------- conversion kernels ----------------
// h (fp32) -> Afrag (fp16, fragment order, zero-padded)
__global__ void convert_a_kernel(const float* __restrict__ A, int n) {
    int c = blockIdx.x * blockDim.x + threadIdx.x;
    if (c >= NTILES_PAD * 16 * 32) return;
    int lane = c & 31;
    int kc   = (c >> 5) & 15;
    int t    = c >> 9;
    int g    = lane >> 2;
    int tig  = lane & 3;
    int r0 = t * 16 + g, r1 = r0 + 8;
    int kb = kc * 16 + 2 * tig;
    float2 a00 = make_float2(0.f, 0.f), a01 = a00, a10 = a00, a11 = a00;
    if (r0 < n) {
        a00 = *(const float2*)(A + (size_t)r0 * HIDDEN + kb);
        a01 = *(const float2*)(A + (size_t)r0 * HIDDEN + kb + 8);
    }
    if (r1 < n) {
        a10 = *(const float2*)(A + (size_t)r1 * HIDDEN + kb);
        a11 = *(const float2*)(A + (size_t)r1 * HIDDEN + kb + 8);
    }
    uint4 o;
    o.x = packh2(a00.x, a00.y);
    o.y = packh2(a10.x, a10.y);
    o.z = packh2(a01.x, a01.y);
    o.w = packh2(a11.x, a11.y);
    ((uint4*)g_af)[c] = o;
}

// Wq/Wk/Wv (fp32) -> Wfrag (fp16 fragment order, permuted rows)
__global__ void convert_w_kernel(const float* __restrict__ Wq,
                                 const float* __restrict__ Wk,
                                 const float* __restrict__ Wv) {
    int c = blockIdx.x * blockDim.x + threadIdx.x;
    if (c >= 3 * 32 * 16 * 32) return;
    int lane = c & 31;
    int kc   = (c >> 5) & 15;
    int tn   = (c >> 9) & 31;
    int z    = c >> 14;
    int g    = lane >> 2;
    int tig  = lane & 3;
    int p  = tn * 8 + g;
    int wr = (p & 128) + (((p & 127) & 1) << 6) + ((p & 127) >> 1);
    const float* W = (z == 0) ? Wq : (z == 1) ? Wk : Wv;
    int kb = kc * 16 + 2 * tig;
    float2 f0 = *(const float2*)(W + (size_t)wr * HIDDEN + kb);
    float2 f1 = *(const float2*)(W + (size_t)wr * HIDDEN + kb + 8);
    uint2 o;
    o.x = packh2(f0.x, f0.y);
    o.y = packh2(f1.x, f1.y);
    ((uint2*)g_wf)[c] = o;
}

// ================ QKV GEMM: pure fp16, cp.async 4-stage pipeline ===========
// BM=128 BN=128 BK=16, 8 warps, warp tile 32x64. Fill = raw async copies.
#define STG_SZ 8192    // A 4KB + B 4KB

__global__ void __launch_bounds__(256, 2) gemm_qkv_kernel(
    const float* __restrict__ b0_, const float* __restrict__ b1_, const float* __restrict__ b2_,
    __half* __restrict__ QH, __half* __restrict__ KH, __half* __restrict__ VH,
    int M, float scale0)
{
    __shared__ __align__(16) unsigned char sm[4 * STG_SZ];

    const int z = blockIdx.z;
    const float* bias = (z == 0) ? b0_ : (z == 1) ? b1_ : b2_;
    __half* H         = (z == 0) ? QH : (z == 1) ? KH : VH;
    const float scale = (z == 0) ? scale0 : 1.f;

    const int tid  = threadIdx.x;
    const int lane = tid & 31;
    const int warp = tid >> 5;
    const int g    = lane >> 2;
    const int tig  = lane & 3;
    const int wm   = (warp >> 1) * 32;
    const int wn   = (warp & 1) * 64;

    const int m0 = blockIdx.x * 128;
    const int n0 = blockIdx.y * 128;

    const uint32_t smbase = (uint32_t)__cvta_generic_to_shared(sm);
    const int ftr = warp;            // 0..7

    // global fragment bases
    const char* afbase = (const char*)g_af + ((size_t)((m0 >> 4) + ftr)) * 8192 + lane * 16;
    const char* wfbase = (const char*)g_wf + (size_t)z * 131072;
    const int tng0 = (n0 >> 3) + ftr;        // B tiles ftr, ftr+8 (local)
    const char* wf0 = wfbase + (size_t)tng0 * 4096 + lane * 8;
    const char* wf1 = wfbase + (size_t)(tng0 + 8) * 4096 + lane * 8;

    float acc[2][8][4];
    #pragma unroll
    for (int mt = 0; mt < 2; mt++)
        #pragma unroll
        for (int nt = 0; nt < 8; nt++)
            #pragma unroll
            for (int r = 0; r < 4; r++) acc[mt][nt][r] = 0.f;

    // fill(stage s, k-chunk kc): A cell 16B + 2 B cells 8B, then commit
    #define FILL(s, kc) do {                                               \
        uint32_t dA = smbase + (s) * STG_SZ + ftr * 512 + lane * 16;       \
        CP_ASYNC16(dA, afbase + (kc) * 512);                               \
        uint32_t dB0 = smbase + (s) * STG_SZ + 4096 + ftr * 256 + lane * 8;\
        CP_ASYNC8(dB0, wf0 + (kc) * 256);                                  \
        uint32_t dB1 = dB0 + 2048;                                         \
        CP_ASYNC8(dB1, wf1 + (kc) * 256);                                  \
        CP_COMMIT();                                                       \
    } while (0)

    FILL(0, 0);
    FILL(1, 1);
    FILL(2, 2);

    #pragma unroll 1
    for (int it = 0; it < 16; it++) {
        CP_WAIT2();
        __syncthreads();

        {
            const unsigned char* st = sm + (it & 3) * STG_SZ;
            uint4 ah[2];
            #pragma unroll
            for (int mt = 0; mt < 2; mt++) {
                int tr = (wm >> 4) + mt;
                ah[mt] = *(const uint4*)(st + tr * 512 + lane * 16);
            }
            #pragma unroll
            for (int nt = 0; nt < 8; nt++) {
                int tn = (wn >> 3) + nt;
                uint2 bh = *(const uint2*)(st + 4096 + tn * 256 + lane * 8);
                MMA_F16(acc[0][nt], ah[0], bh.x, bh.y);
                MMA_F16(acc[1][nt], ah[1], bh.x, bh.y);
            }
        }

        if (it + 3 < 16) {
            FILL((it + 3) & 3, it + 3);
        } else {
            CP_COMMIT();   // empty group keeps wait_group arithmetic valid
        }
    }
    #undef FILL

    // fp16 permuted epilogue
    #pragma unroll
    for (int mt = 0; mt < 2; mt++) {
        int r0 = m0 + wm + mt * 16 + g;
        #pragma unroll
        for (int nt = 0; nt < 8; nt++) {
            int jl = wn + nt * 8 + 2 * tig;
            float bx = bias[n0 + (jl >> 1)];
            float by = bias[n0 + 64 + (jl >> 1)];
            if (r0 < M) {
                *(__half2*)(H + (size_t)r0 * HIDDEN + n0 + jl) =
                    __halves2half2(__float2half_rn((acc[mt][nt][0] + bx) * scale),
                                   __float2half_rn((acc[mt][nt][1] + by) * scale));
            }
            if (r0 + 8 < M) {
                *(__half2*)(H + (size_t)(r0 + 8) * HIDDEN + n0 + jl) =
                    __halves2half2(__float2half_rn((acc[mt][nt][2] + bx) * scale),
                                   __float2half_rn((acc[mt][nt][3] + by) * scale));
            }
        }
    }
}

// ================ O-proj GEMM: fp16 A (permuted) x fp16 W, 1-term ===========
#define OST_AH 0
#define OST_BH 4096
#define OST_SZ 8192

__global__ void __launch_bounds__(256, 2) gemm_oproj_kernel(
    const __half* __restrict__ AH,
    const float* __restrict__ W, const float* __restrict__ bias,
    float* __restrict__ C, int M)
{
    __shared__ __align__(16) unsigned char sm[2][OST_SZ];

    const int tid  = threadIdx.x;
    const int lane = tid & 31;
    const int warp = tid >> 5;
    const int g    = lane >> 2;
    const int tig  = lane & 3;
    const int wm   = (warp >> 1) * 32;
    const int wn   = (warp & 1) * 64;

    const int m0 = blockIdx.x * 128;
    const int n0 = blockIdx.y * 128;

    const int ftr = tid >> 5;
    const int fl  = lane;
    const int arow_lo = m0 + ftr * 16 + g;
    const int arow_hi = arow_lo + 8;
    const bool vlo = arow_lo < M, vhi = arow_hi < M;
    const uint32_t* Aw_lo = (const uint32_t*)(AH + (size_t)arow_lo * HIDDEN);
    const uint32_t* Aw_hi = (const uint32_t*)(AH + (size_t)arow_hi * HIDDEN);

    const int wr0 = n0 + ftr * 8 + g;
    const int wr1 = n0 + (ftr + 8) * 8 + g;
    const float* Wr0 = W + (size_t)wr0 * HIDDEN;
    const float* Wr1 = W + (size_t)wr1 * HIDDEN;

    uint32_t xa0, xa1, xa2, xa3;
    float2 xb0, xb1, xb2, xb3;

    #define WPAIR(Wr, w) make_float2(Wr[(w) + (((w) >= 64) ? 64 : 0)],           \
                                     Wr[(w) + (((w) >= 64) ? 64 : 0) + 64])

    {
        int w0 = tig, w1 = tig + 4;
        xa0 = vlo ? Aw_lo[w0] : 0u;
        xa1 = vhi ? Aw_hi[w0] : 0u;
        xa2 = vlo ? Aw_lo[w1] : 0u;
        xa3 = vhi ? Aw_hi[w1] : 0u;
        xb0 = WPAIR(Wr0, w0); xb1 = WPAIR(Wr0, w1);
        xb2 = WPAIR(Wr1, w0); xb3 = WPAIR(Wr1, w1);
    }

    float acc[2][8][4];
    #pragma unroll
    for (int mt = 0; mt < 2; mt++)
        #pragma unroll
        for (int nt = 0; nt < 8; nt++)
            #pragma unroll
            for (int r = 0; r < 4; r++) acc[mt][nt][r] = 0.f;

    {
        unsigned char* st = sm[0];
        *(uint4*)(st + OST_AH + ftr * 512 + fl * 16) = make_uint4(xa0, xa1, xa2, xa3);
        uint2 bh0, bh1;
        bh0.x = packh2(xb0.x, xb0.y);
        bh0.y = packh2(xb1.x, xb1.y);
        bh1.x = packh2(xb2.x, xb2.y);
        bh1.y = packh2(xb3.x, xb3.y);
        *(uint2*)(st + OST_BH + ftr * 256 + fl * 8) = bh0;
        *(uint2*)(st + OST_BH + (ftr + 8) * 256 + fl * 8) = bh1;
    }
    __syncthreads();

    #pragma unroll 1
    for (int it = 0; it < 16; it++) {
        if (it + 1 < 16) {
            int w0 = (it + 1) * 8 + tig, w1 = w0 + 4;
            xa0 = vlo ? Aw_lo[w0] : 0u;
            xa1 = vhi ? Aw_hi[w0] : 0u;
            xa2 = vlo ? Aw_lo[w1] : 0u;
            xa3 = vhi ? Aw_hi[w1] : 0u;
            xb0 = WPAIR(Wr0, w0); xb1 = WPAIR(Wr0, w1);
            xb2 = WPAIR(Wr1, w0); xb3 = WPAIR(Wr1, w1);
        }

        {
            const unsigned char* st = sm[it & 1];
            uint4 ah[2];
            #pragma unroll
            for (int mt = 0; mt < 2; mt++) {
                int tr = (wm >> 4) + mt;
                ah[mt] = *(const uint4*)(st + OST_AH + tr * 512 + lane * 16);
            }
            #pragma unroll
            for (int nt = 0; nt < 8; nt++) {
                int tn = (wn >> 3) + nt;
                uint2 bh = *(const uint2*)(st + OST_BH + tn * 256 + lane * 8);
                MMA_F16(acc[0][nt], ah[0], bh.x, bh.y);
                MMA_F16(acc[1][nt], ah[1], bh.x, bh.y);
            }
        }

        if (it + 1 < 16) {
            unsigned char* st = sm[(it + 1) & 1];
            *(uint4*)(st + OST_AH + ftr * 512 + fl * 16) = make_uint4(xa0, xa1, xa2, xa3);
            uint2 bh0, bh1;
            bh0.x = packh2(xb0.x, xb0.y);
            bh0.y = packh2(xb1.x, xb1.y);
            bh1.x = packh2(xb2.x, xb2.y);
            bh1.y = packh2(xb3.x, xb3.y);
            *(uint2*)(st + OST_BH + ftr * 256 + fl * 8) = bh0;
            *(uint2*)(st + OST_BH + (ftr + 8) * 256 + fl * 8) = bh1;
        }
        __syncthreads();
    }
    #undef WPAIR

    // fp32 epilogue
    #pragma unroll
    for (int mt = 0; mt < 2; mt++) {
        int r0 = m0 + wm + mt * 16 + g;
        #pragma unroll
        for (int nt = 0; nt < 8; nt++) {
            int c = n0 + wn + nt * 8 + 2 * tig;
            float bx = bias[c], by = bias[c + 1];
            if (r0 < M) {
                float2 o0;
                o0.x = acc[mt][nt][0] + bx;
                o0.y = acc[mt][nt][1] + by;
                *(float2*)(C + (size_t)r0 * HIDDEN + c) = o0;
            }
            if (r0 + 8 < M) {
                float2 o1;
                o1.x = acc[mt][nt][2] + bx;
                o1.y = acc[mt][nt][3] + by;
                *(float2*)(C + (size_t)(r0 + 8) * HIDDEN + c) = o1;
            }
        }
    }
}

// ---------------- attention: one warp per node, all-fp16, 8-edge unroll -----
__global__ void __launch_bounds__(256) attn_kernel(int n) {
    int gw   = (blockIdx.x * blockDim.x + threadIdx.x) >> 5;
    int lane = threadIdx.x & 31;
    if (gw >= n) return;
    const int i = gw;
    const int start = g_offs[i];
    const int end   = g_offs[i + 1];

    const __half2* QB = (const __half2*)g_qh;
    const __half2* KB = (const __half2*)g_kh;
    const __half2* VB = (const __half2*)g_vh;

    float2 ql[4];
    #pragma unroll
    for (int c = 0; c < 4; c++)
        ql[c] = __half22float2(QB[(size_t)i * 128 + c * 32 + lane]);

    float m = __int_as_float(0xff800000);
    float d = 0.f;
    float2 acc[4] = {};

    int p = start;
    for (; p + 7 < end; p += 8) {
        int cn[8];
        #pragma unroll
        for (int e = 0; e < 8; e++) cn[e] = g_ccol[p + e];

        float s[8] = {0.f, 0.f, 0.f, 0.f, 0.f, 0.f, 0.f, 0.f};
        #pragma unroll
        for (int c = 0; c < 4; c++) {
            int o = c * 32 + lane;
            #pragma unroll
            for (int e = 0; e < 8; e++) {
                float2 kf = __half22float2(__ldg(KB + (size_t)cn[e] * 128 + o));
                s[e] += ql[c].x * kf.x + ql[c].y * kf.y;
            }
        }
        #pragma unroll
        for (int e = 0; e < 8; e++) {
            s[e] += __shfl_xor_sync(0xffffffffu, s[e], 16);
            s[e] += __shfl_xor_sync(0xffffffffu, s[e], 8);
        }

        float m2 = m;
        #pragma unroll
        for (int e = 0; e < 8; e++) m2 = fmaxf(m2, s[e]);
        float cf = __expf(m - m2);
        float w[8], sw = 0.f;
        #pragma unroll
        for (int e = 0; e < 8; e++) { w[e] = __expf(s[e] - m2); sw += w[e]; }
        d = d * cf + sw;
        m = m2;

        #pragma unroll
        for (int c = 0; c < 4; c++) {
            int o = c * 32 + lane;
            float tx = acc[c].x * cf, ty = acc[c].y * cf;
            #pragma unroll
            for (int e = 0; e < 8; e++) {
                float2 vf = __half22float2(__ldg(VB + (size_t)cn[e] * 128 + o));
                tx += w[e] * vf.x;
                ty += w[e] * vf.y;
            }
            acc[c].x = tx; acc[c].y = ty;
        }
    }
    for (; p < end; p++) {
        int c0 = g_ccol[p];
        float s0 = 0.f;
        #pragma unroll
        for (int c = 0; c < 4; c++) {
            float2 kf = __half22float2(__ldg(KB + (size_t)c0 * 128 + c * 32 + lane));
            s0 += ql[c].x * kf.x + ql[c].y * kf.y;
        }
        s0 += __shfl_xor_sync(0xffffffffu, s0, 16);
        s0 += __shfl_xor_sync(0xffffffffu, s0, 8);
        float m2 = fmaxf(m, s0);
        float cf = __expf(m - m2);
        float w0 = __expf(s0 - m2);
        d = d * cf + w0;
        m = m2;
        #pragma unroll
        for (int c = 0; c < 4; c++) {
            float2 vf = __half22float2(__ldg(VB + (size_t)c0 * 128 + c * 32 + lane));
            acc[c].x = acc[c].x * cf + w0 * vf.x;
            acc[c].y = acc[c].y * cf + w0 * vf.y;
        }
    }

    float rd = (end > start) ? 1.f / d : 0.f;
    __half2* AO = (__half2*)g_aoh;
    #pragma unroll
    for (int c = 0; c < 4; c++) {
        AO[(size_t)i * 128 + c * 32 + lane] =
            __halves2half2(__float2half_rn(acc[c].x * rd),
                           __float2half_rn(acc[c].y * rd));
    }
}

// ---------------- launch ----------------
extern "C" void kernel_launch(void* const* d_in, const int* in_sizes, int n_in,
                              void* d_out, int out_size) {
    const float* h   = (const float*)d_in[0];
    const int*   row = (const int*)d_in[1];
    const int*   col = (const int*)d_in[2];
    const float* Wq  = (const float*)d_in[3];
    const float* bq  = (const float*)d_in[4];
    const float* Wk  = (const float*)d_in[5];
    const float* bk  = (const float*)d_in[6];
    const float* Wv  = (const float*)d_in[7];
    const float* bv  = (const float*)d_in[8];
    const float* Wo  = (const float*)d_in[9];
    const float* bo  = (const float*)d_in[10];
    float* out = (float*)d_out;

    const int N = in_sizes[0] / HIDDEN;
    const int E = in_sizes[1];

    __half *pqh, *pkh, *pvh, *paoh;
    int *pdeg;
    cudaGetSymbolAddress((void**)&pqh, g_qh);
    cudaGetSymbolAddress((void**)&pkh, g_kh);
    cudaGetSymbolAddress((void**)&pvh, g_vh);
    cudaGetSymbolAddress((void**)&paoh, g_aoh);
    cudaGetSymbolAddress((void**)&pdeg, g_deg);

    static cudaStream_t s2 = nullptr;
    static cudaEvent_t evFork = nullptr, evJoin = nullptr;
    if (!s2) {
        cudaStreamCreateWithFlags(&s2, cudaStreamNonBlocking);
        cudaEventCreateWithFlags(&evFork, cudaEventDisableTiming);
        cudaEventCreateWithFlags(&evJoin, cudaEventDisableTiming);
    }

    // fork: CSR build on s2
    cudaEventRecord(evFork, 0);
    cudaStreamWaitEvent(s2, evFork, 0);
    cudaMemsetAsync(pdeg, 0, (size_t)N * sizeof(int), s2);
    count_deg_kernel<<<(E + 255) / 256, 256, 0, s2>>>(row, E);
    scan_kernel<<<1, 1024, 0, s2>>>(N);
    scatter_kernel<<<(E + 255) / 256, 256, 0, s2>>>(row, col, E);
    cudaEventRecord(evJoin, s2);

    // main: conversions, then QKV
    convert_a_kernel<<<(NTILES_PAD * 16 * 32 + 255) / 256, 256>>>(h, N);
    convert_w_kernel<<<(3 * 32 * 16 * 32 + 255) / 256, 256>>>(Wq, Wk, Wv);

    const float scaling = 0.17677669529663687f;  // 32^-0.5
    dim3 gqkv((N + 127) / 128, HIDDEN / 128, 3);
    gemm_qkv_kernel<<<gqkv, 256>>>(bq, bk, bv, pqh, pkh, pvh, N, scaling);

    cudaStreamWaitEvent(0, evJoin, 0);
    attn_kernel<<<(N + 7) / 8, 256>>>(N);

    dim3 go((N + 127) / 128, HIDDEN / 128, 1);
    gemm_oproj_kernel<<<go, 256>>>(paoh, Wo, bo, out, N);
}

// round 15
// speedup vs baseline: 2.0462x; 1.1789x over previous
#include <cuda_runtime.h>
#include <cuda_fp16.h>
#include <cstdint>

#define HIDDEN 256
#define HEADS 8
#define MAXN 50000
#define MAXE 800000
#define NTILES_PAD 3136          // ceil(50000/16) padded

// ---------------- scratch ----------------
// Head-major pair layout (per row of 256 halfs): word W (0..127) = half2 pair
//   (f, f+64), f = j*8 + h + (j>=8 ? 64 : 0), where h = W>>4, j = W&15.
// => lane l's uint4 (words 4l..4l+3) covers 8 feats ALL of head g = l>>2.
__device__ __half g_qh[(size_t)MAXN * HIDDEN];
__device__ __half g_kh[(size_t)MAXN * HIDDEN];
__device__ __half g_vh[(size_t)MAXN * HIDDEN];
__device__ __half g_aoh[(size_t)MAXN * HIDDEN];
// A (h) fragment order: cell c=(t*16+kc)*32+lane, 16B
__device__ __half g_af[(size_t)NTILES_PAD * 16 * 32 * 8];
// W (q,k,v) fragments, permuted rows: cell ((z,tn,kc,lane)), 8B
__device__ __half g_wf[3 * 32 * 16 * 32 * 4];
// aoh fragment order (for O-proj A)
__device__ __half g_aof[(size_t)NTILES_PAD * 16 * 32 * 8];
// Wo fragments with inverse k-permutation baked
__device__ __half g_wof[32 * 16 * 32 * 4];
__device__ int    g_deg[MAXN];
__device__ int    g_offs[MAXN + 1];
__device__ int    g_cursor[MAXN];
__device__ int    g_ccol[MAXE];

// feature for half-slot p (0..255): b=p&1, W=p>>1, h=W>>4, j=W&15
__device__ __host__ __forceinline__ int slot_feat(int p) {
    int b = p & 1, W = p >> 1, h = W >> 4, j = W & 15;
    return j * 8 + h + ((j >= 8) ? 64 : 0) + b * 64;
}

// ---------------- CSR build ----------------
__global__ void count_deg_kernel(const int* __restrict__ row, int e) {
    int i = blockIdx.x * blockDim.x + threadIdx.x;
    if (i < e) atomicAdd(&g_deg[row[i]], 1);
}

__global__ void scan_kernel(int n) {
    __shared__ int wsum[32];
    int lane = threadIdx.x & 31;
    int wid  = threadIdx.x >> 5;
    int carry = 0;
    for (int base = 0; base < n; base += 1024) {
        int i = base + (int)threadIdx.x;
        int v = (i < n) ? g_deg[i] : 0;
        int x = v;
        #pragma unroll
        for (int d = 1; d < 32; d <<= 1) {
            int y = __shfl_up_sync(0xffffffffu, x, d);
            if (lane >= d) x += y;
        }
        if (lane == 31) wsum[wid] = x;
        __syncthreads();
        if (wid == 0) {
            int wv = wsum[lane];
            #pragma unroll
            for (int d = 1; d < 32; d <<= 1) {
                int y = __shfl_up_sync(0xffffffffu, wv, d);
                if (lane >= d) wv += y;
            }
            wsum[lane] = wv;
        }
        __syncthreads();
        int inc = x + (wid > 0 ? wsum[wid - 1] : 0) + carry;
        if (i < n) {
            int excl = inc - v;
            g_offs[i]   = excl;
            g_cursor[i] = excl;
        }
        carry += wsum[31];
        __syncthreads();
    }
    if (threadIdx.x == 0) g_offs[n] = carry;
}

__global__ void scatter_kernel(const int* __restrict__ row, const int* __restrict__ col, int e) {
    int i = blockIdx.x * blockDim.x + threadIdx.x;
    if (i < e) {
        int slot = atomicAdd(&g_cursor[row[i]], 1);
        g_ccol[slot] = col[i];
    }
}

// ---------------- helpers ----------------
__device__ __forceinline__ uint32_t packh2(float x, float y) {
    __half2 h = __halves2half2(__float2half_rn(x), __float2half_rn(y));
    return *(uint32_t*)&h;
}

#define MMA_F16(ACC, AV, B0, B1)                                           \
    asm volatile(                                                          \
        "mma.sync.aligned.m16n8k16.row.col.f32.f16.f16.f32 "              \
        "{%0,%1,%2,%3}, {%4,%5,%6,%7}, {%8,%9}, {%0,%1,%2,%3};"           \
        : "+f"(ACC[0]), "+f"(ACC[1]), "+f"(ACC[2]), "+f"(ACC[3])          \
        : "r"(AV.x), "r"(AV.y), "r"(AV.z), "r"(AV.w),                     \
          "r"(B0), "r"(B1))

#define CP_ASYNC16(dst, src)                                               \
    asm volatile("cp.async.ca.shared.global [%0], [%1], 16;"              \
                 :: "r"(dst), "l"(src))
#define CP_ASYNC8(dst, src)                                                \
    asm volatile("cp.async.ca.shared.global [%0], [%1], 8;"               \
                 :: "r"(dst), "l"(src))
#define CP_COMMIT()  asm volatile("cp.async.commit_group;" ::: "memory")
#define CP_WAIT2()   asm volatile("cp.async.wait_group 2;" ::: "memory")

// ---------------- conversion kernels ----------------
// h (fp32) -> A fragments (fp16, zero-padded)
__global__ void convert_a_kernel(const float* __restrict__ A, int n) {
    int c = blockIdx.x * blockDim.x + threadIdx.x;
    if (c >= NTILES_PAD * 16 * 32) return;
    int lane = c & 31;
    int kc   = (c >> 5) & 15;
    int t    = c >> 9;
    int g    = lane >> 2;
    int tig  = lane & 3;
    int r0 = t * 16 + g, r1 = r0 + 8;
    int kb = kc * 16 + 2 * tig;
    float2 a00 = make_float2(0.f, 0.f), a01 = a00, a10 = a00, a11 = a00;
    if (r0 < n) {
        a00 = *(const float2*)(A + (size_t)r0 * HIDDEN + kb);
        a01 = *(const float2*)(A + (size_t)r0 * HIDDEN + kb + 8);
    }
    if (r1 < n) {
        a10 = *(const float2*)(A + (size_t)r1 * HIDDEN + kb);
        a11 = *(const float2*)(A + (size_t)r1 * HIDDEN + kb + 8);
    }
    uint4 o;
    o.x = packh2(a00.x, a00.y);
    o.y = packh2(a10.x, a10.y);
    o.z = packh2(a01.x, a01.y);
    o.w = packh2(a11.x, a11.y);
    ((uint4*)g_af)[c] = o;
}

// Wq/Wk/Wv -> fragments with head-major output permutation
__global__ void convert_w_kernel(const float* __restrict__ Wq,
                                 const float* __restrict__ Wk,
                                 const float* __restrict__ Wv) {
    int c = blockIdx.x * blockDim.x + threadIdx.x;
    if (c >= 3 * 32 * 16 * 32) return;
    int lane = c & 31;
    int kc   = (c >> 5) & 15;
    int tn   = (c >> 9) & 31;
    int z    = c >> 14;
    int g    = lane >> 2;
    int tig  = lane & 3;
    int p  = tn * 8 + g;           // output half-slot
    int wr = slot_feat(p);
    const float* W = (z == 0) ? Wq : (z == 1) ? Wk : Wv;
    int kb = kc * 16 + 2 * tig;
    float2 f0 = *(const float2*)(W + (size_t)wr * HIDDEN + kb);
    float2 f1 = *(const float2*)(W + (size_t)wr * HIDDEN + kb + 8);
    uint2 o;
    o.x = packh2(f0.x, f0.y);
    o.y = packh2(f1.x, f1.y);
    ((uint2*)g_wf)[c] = o;
}

// aoh (fp16 head-major) -> A fragments (gather only)
__global__ void convert_ao_kernel(int n) {
    int c = blockIdx.x * blockDim.x + threadIdx.x;
    if (c >= NTILES_PAD * 16 * 32) return;
    int lane = c & 31;
    int kc   = (c >> 5) & 15;
    int t    = c >> 9;
    int g    = lane >> 2;
    int tig  = lane & 3;
    int r0 = t * 16 + g, r1 = r0 + 8;
    int wq = kc * 8 + tig;              // word index (half2)
    const uint32_t* AO = (const uint32_t*)g_aoh;
    uint4 o = make_uint4(0u, 0u, 0u, 0u);
    if (r0 < n) {
        o.x = AO[(size_t)r0 * 128 + wq];
        o.z = AO[(size_t)r0 * 128 + wq + 4];
    }
    if (r1 < n) {
        o.y = AO[(size_t)r1 * 128 + wq];
        o.w = AO[(size_t)r1 * 128 + wq + 4];
    }
    ((uint4*)g_aof)[c] = o;
}

// Wo -> fragments with inverse slot permutation on the K dimension
__global__ void convert_wo_kernel(const float* __restrict__ Wo) {
    int c = blockIdx.x * blockDim.x + threadIdx.x;
    if (c >= 32 * 16 * 32) return;
    int lane = c & 31;
    int kc   = (c >> 5) & 15;
    int tn   = c >> 9;
    int g    = lane >> 2;
    int tig  = lane & 3;
    int col = tn * 8 + g;               // plain output column
    const float* Wr = Wo + (size_t)col * HIDDEN;
    int p0 = kc * 16 + 2 * tig;         // k slots p0, p0+1 and p0+8, p0+9
    int fA = slot_feat(p0);             // p0 even -> f; p0+1 -> f+64
    int p1 = p0 + 8;
    int fB = slot_feat(p1);
    uint2 o;
    o.x = packh2(Wr[fA], Wr[fA + 64]);
    o.y = packh2(Wr[fB], Wr[fB + 64]);
    ((uint2*)g_wof)[c] = o;
}

// ================ fragment cp.async GEMM (shared body) =====================
#define STG_SZ 8192    // A 4KB + B 4KB

// QKV: fp16 permuted epilogue
__global__ void __launch_bounds__(256, 2) gemm_qkv_kernel(
    const float* __restrict__ b0_, const float* __restrict__ b1_, const float* __restrict__ b2_,
    __half* __restrict__ QH, __half* __restrict__ KH, __half* __restrict__ VH,
    int M, float scale0)
{
    __shared__ __align__(16) unsigned char sm[4 * STG_SZ];

    const int z = blockIdx.z;
    const float* bias = (z == 0) ? b0_ : (z == 1) ? b1_ : b2_;
    __half* H         = (z == 0) ? QH : (z == 1) ? KH : VH;
    const float scale = (z == 0) ? scale0 : 1.f;

    const int tid  = threadIdx.x;
    const int lane = tid & 31;
    const int warp = tid >> 5;
    const int g    = lane >> 2;
    const int tig  = lane & 3;
    const int wm   = (warp >> 1) * 32;
    const int wn   = (warp & 1) * 64;

    const int m0 = blockIdx.x * 128;
    const int n0 = blockIdx.y * 128;

    const uint32_t smbase = (uint32_t)__cvta_generic_to_shared(sm);
    const int ftr = warp;

    const char* afbase = (const char*)g_af + ((size_t)((m0 >> 4) + ftr)) * 8192 + lane * 16;
    const char* wfbase = (const char*)g_wf + (size_t)z * 131072;
    const int tng0 = (n0 >> 3) + ftr;
    const char* wf0 = wfbase + (size_t)tng0 * 4096 + lane * 8;
    const char* wf1 = wfbase + (size_t)(tng0 + 8) * 4096 + lane * 8;

    float acc[2][8][4];
    #pragma unroll
    for (int mt = 0; mt < 2; mt++)
        #pragma unroll
        for (int nt = 0; nt < 8; nt++)
            #pragma unroll
            for (int r = 0; r < 4; r++) acc[mt][nt][r] = 0.f;

    #define FILL(s, kc) do {                                               \
        uint32_t dA = smbase + (s) * STG_SZ + ftr * 512 + lane * 16;       \
        CP_ASYNC16(dA, afbase + (kc) * 512);                               \
        uint32_t dB0 = smbase + (s) * STG_SZ + 4096 + ftr * 256 + lane * 8;\
        CP_ASYNC8(dB0, wf0 + (kc) * 256);                                  \
        uint32_t dB1 = dB0 + 2048;                                         \
        CP_ASYNC8(dB1, wf1 + (kc) * 256);                                  \
        CP_COMMIT();                                                       \
    } while (0)

    FILL(0, 0);
    FILL(1, 1);
    FILL(2, 2);

    #pragma unroll 1
    for (int it = 0; it < 16; it++) {
        CP_WAIT2();
        __syncthreads();
        {
            const unsigned char* st = sm + (it & 3) * STG_SZ;
            uint4 ah[2];
            #pragma unroll
            for (int mt = 0; mt < 2; mt++) {
                int tr = (wm >> 4) + mt;
                ah[mt] = *(const uint4*)(st + tr * 512 + lane * 16);
            }
            #pragma unroll
            for (int nt = 0; nt < 8; nt++) {
                int tn = (wn >> 3) + nt;
                uint2 bh = *(const uint2*)(st + 4096 + tn * 256 + lane * 8);
                MMA_F16(acc[0][nt], ah[0], bh.x, bh.y);
                MMA_F16(acc[1][nt], ah[1], bh.x, bh.y);
            }
        }
        if (it + 3 < 16) {
            FILL((it + 3) & 3, it + 3);
        } else {
            CP_COMMIT();
        }
    }
    #undef FILL

    // fp16 head-major epilogue
    #pragma unroll
    for (int mt = 0; mt < 2; mt++) {
        int r0 = m0 + wm + mt * 16 + g;
        #pragma unroll
        for (int nt = 0; nt < 8; nt++) {
            int p = n0 + wn + nt * 8 + 2 * tig;   // even slot
            int f0 = slot_feat(p);
            float bx = bias[f0];
            float by = bias[f0 + 64];
            if (r0 < M) {
                *(__half2*)(H + (size_t)r0 * HIDDEN + p) =
                    __halves2half2(__float2half_rn((acc[mt][nt][0] + bx) * scale),
                                   __float2half_rn((acc[mt][nt][1] + by) * scale));
            }
            if (r0 + 8 < M) {
                *(__half2*)(H + (size_t)(r0 + 8) * HIDDEN + p) =
                    __halves2half2(__float2half_rn((acc[mt][nt][2] + bx) * scale),
                                   __float2half_rn((acc[mt][nt][3] + by) * scale));
            }
        }
    }
}

// O-proj: same pipeline, fp32 epilogue
__global__ void __launch_bounds__(256, 2) gemm_oproj_kernel(
    const float* __restrict__ bias, float* __restrict__ C, int M)
{
    __shared__ __align__(16) unsigned char sm[4 * STG_SZ];

    const int tid  = threadIdx.x;
    const int lane = tid & 31;
    const int warp = tid >> 5;
    const int g    = lane >> 2;
    const int tig  = lane & 3;
    const int wm   = (warp >> 1) * 32;
    const int wn   = (warp & 1) * 64;

    const int m0 = blockIdx.x * 128;
    const int n0 = blockIdx.y * 128;

    const uint32_t smbase = (uint32_t)__cvta_generic_to_shared(sm);
    const int ftr = warp;

    const char* afbase = (const char*)g_aof + ((size_t)((m0 >> 4) + ftr)) * 8192 + lane * 16;
    const int tng0 = (n0 >> 3) + ftr;
    const char* wf0 = (const char*)g_wof + (size_t)tng0 * 4096 + lane * 8;
    const char* wf1 = (const char*)g_wof + (size_t)(tng0 + 8) * 4096 + lane * 8;

    float acc[2][8][4];
    #pragma unroll
    for (int mt = 0; mt < 2; mt++)
        #pragma unroll
        for (int nt = 0; nt < 8; nt++)
            #pragma unroll
            for (int r = 0; r < 4; r++) acc[mt][nt][r] = 0.f;

    #define FILL(s, kc) do {                                               \
        uint32_t dA = smbase + (s) * STG_SZ + ftr * 512 + lane * 16;       \
        CP_ASYNC16(dA, afbase + (kc) * 512);                               \
        uint32_t dB0 = smbase + (s) * STG_SZ + 4096 + ftr * 256 + lane * 8;\
        CP_ASYNC8(dB0, wf0 + (kc) * 256);                                  \
        uint32_t dB1 = dB0 + 2048;                                         \
        CP_ASYNC8(dB1, wf1 + (kc) * 256);                                  \
        CP_COMMIT();                                                       \
    } while (0)

    FILL(0, 0);
    FILL(1, 1);
    FILL(2, 2);

    #pragma unroll 1
    for (int it = 0; it < 16; it++) {
        CP_WAIT2();
        __syncthreads();
        {
            const unsigned char* st = sm + (it & 3) * STG_SZ;
            uint4 ah[2];
            #pragma unroll
            for (int mt = 0; mt < 2; mt++) {
                int tr = (wm >> 4) + mt;
                ah[mt] = *(const uint4*)(st + tr * 512 + lane * 16);
            }
            #pragma unroll
            for (int nt = 0; nt < 8; nt++) {
                int tn = (wn >> 3) + nt;
                uint2 bh = *(const uint2*)(st + 4096 + tn * 256 + lane * 8);
                MMA_F16(acc[0][nt], ah[0], bh.x, bh.y);
                MMA_F16(acc[1][nt], ah[1], bh.x, bh.y);
            }
        }
        if (it + 3 < 16) {
            FILL((it + 3) & 3, it + 3);
        } else {
            CP_COMMIT();
        }
    }
    #undef FILL

    #pragma unroll
    for (int mt = 0; mt < 2; mt++) {
        int r0 = m0 + wm + mt * 16 + g;
        #pragma unroll
        for (int nt = 0; nt < 8; nt++) {
            int c = n0 + wn + nt * 8 + 2 * tig;
            float bx = bias[c], by = bias[c + 1];
            if (r0 < M) {
                float2 o0;
                o0.x = acc[mt][nt][0] + bx;
                o0.y = acc[mt][nt][1] + by;
                *(float2*)(C + (size_t)r0 * HIDDEN + c) = o0;
            }
            if (r0 + 8 < M) {
                float2 o1;
                o1.x = acc[mt][nt][2] + bx;
                o1.y = acc[mt][nt][3] + by;
                *(float2*)(C + (size_t)(r0 + 8) * HIDDEN + c) = o1;
            }
        }
    }
}

// ---------------- attention: head-major, 1x LDG.128/row/lane, 8-edge -------
__global__ void __launch_bounds__(256) attn_kernel(int n) {
    int gw   = (blockIdx.x * blockDim.x + threadIdx.x) >> 5;
    int lane = threadIdx.x & 31;
    if (gw >= n) return;
    const int i = gw;
    const int start = g_offs[i];
    const int end   = g_offs[i + 1];

    const uint4* QB = (const uint4*)g_qh;   // 32 uint4 per row
    const uint4* KB = (const uint4*)g_kh;
    const uint4* VB = (const uint4*)g_vh;

    // lane's 8 feats (head g = lane>>2)
    float2 q[4];
    {
        uint4 qv = QB[(size_t)i * 32 + lane];
        q[0] = __half22float2(*(__half2*)&qv.x);
        q[1] = __half22float2(*(__half2*)&qv.y);
        q[2] = __half22float2(*(__half2*)&qv.z);
        q[3] = __half22float2(*(__half2*)&qv.w);
    }

    float m = __int_as_float(0xff800000);
    float d = 0.f;
    float2 acc[4] = {};

    int p = start;
    for (; p + 7 < end; p += 8) {
        int cn[8];
        #pragma unroll
        for (int e = 0; e < 8; e++) cn[e] = g_ccol[p + e];

        uint4 kv[8];
        #pragma unroll
        for (int e = 0; e < 8; e++) kv[e] = __ldg(&KB[(size_t)cn[e] * 32 + lane]);

        float s[8];
        #pragma unroll
        for (int e = 0; e < 8; e++) {
            float2 k0 = __half22float2(*(__half2*)&kv[e].x);
            float2 k1 = __half22float2(*(__half2*)&kv[e].y);
            float2 k2 = __half22float2(*(__half2*)&kv[e].z);
            float2 k3 = __half22float2(*(__half2*)&kv[e].w);
            s[e] = q[0].x * k0.x + q[0].y * k0.y
                 + q[1].x * k1.x + q[1].y * k1.y
                 + q[2].x * k2.x + q[2].y * k2.y
                 + q[3].x * k3.x + q[3].y * k3.y;
        }
        #pragma unroll
        for (int e = 0; e < 8; e++) {
            s[e] += __shfl_xor_sync(0xffffffffu, s[e], 1);
            s[e] += __shfl_xor_sync(0xffffffffu, s[e], 2);
        }

        float m2 = m;
        #pragma unroll
        for (int e = 0; e < 8; e++) m2 = fmaxf(m2, s[e]);
        float cf = __expf(m - m2);
        float w[8], sw = 0.f;
        #pragma unroll
        for (int e = 0; e < 8; e++) { w[e] = __expf(s[e] - m2); sw += w[e]; }
        d = d * cf + sw;
        m = m2;

        #pragma unroll
        for (int c = 0; c < 4; c++) { acc[c].x *= cf; acc[c].y *= cf; }
        #pragma unroll
        for (int e = 0; e < 8; e++) {
            uint4 vv = __ldg(&VB[(size_t)cn[e] * 32 + lane]);
            float2 v0 = __half22float2(*(__half2*)&vv.x);
            float2 v1 = __half22float2(*(__half2*)&vv.y);
            float2 v2 = __half22float2(*(__half2*)&vv.z);
            float2 v3 = __half22float2(*(__half2*)&vv.w);
            acc[0].x += w[e] * v0.x; acc[0].y += w[e] * v0.y;
            acc[1].x += w[e] * v1.x; acc[1].y += w[e] * v1.y;
            acc[2].x += w[e] * v2.x; acc[2].y += w[e] * v2.y;
            acc[3].x += w[e] * v3.x; acc[3].y += w[e] * v3.y;
        }
    }
    for (; p < end; p++) {
        int c0 = g_ccol[p];
        uint4 kv = __ldg(&KB[(size_t)c0 * 32 + lane]);
        float2 k0 = __half22float2(*(__half2*)&kv.x);
        float2 k1 = __half22float2(*(__half2*)&kv.y);
        float2 k2 = __half22float2(*(__half2*)&kv.z);
        float2 k3 = __half22float2(*(__half2*)&kv.w);
        float s0 = q[0].x * k0.x + q[0].y * k0.y
                 + q[1].x * k1.x + q[1].y * k1.y
                 + q[2].x * k2.x + q[2].y * k2.y
                 + q[3].x * k3.x + q[3].y * k3.y;
        s0 += __shfl_xor_sync(0xffffffffu, s0, 1);
        s0 += __shfl_xor_sync(0xffffffffu, s0, 2);
        float m2 = fmaxf(m, s0);
        float cf = __expf(m - m2);
        float w0 = __expf(s0 - m2);
        d = d * cf + w0;
        m = m2;
        uint4 vv = __ldg(&VB[(size_t)c0 * 32 + lane]);
        float2 v0 = __half22float2(*(__half2*)&vv.x);
        float2 v1 = __half22float2(*(__half2*)&vv.y);
        float2 v2 = __half22float2(*(__half2*)&vv.z);
        float2 v3 = __half22float2(*(__half2*)&vv.w);
        acc[0].x = acc[0].x * cf + w0 * v0.x; acc[0].y = acc[0].y * cf + w0 * v0.y;
        acc[1].x = acc[1].x * cf + w0 * v1.x; acc[1].y = acc[1].y * cf + w0 * v1.y;
        acc[2].x = acc[2].x * cf + w0 * v2.x; acc[2].y = acc[2].y * cf + w0 * v2.y;
        acc[3].x = acc[3].x * cf + w0 * v3.x; acc[3].y = acc[3].y * cf + w0 * v3.y;
    }

    float rd = (end > start) ? 1.f / d : 0.f;
    uint4 o;
    o.x = packh2(acc[0].x * rd, acc[0].y * rd);
    o.y = packh2(acc[1].x * rd, acc[1].y * rd);
    o.z = packh2(acc[2].x * rd, acc[2].y * rd);
    o.w = packh2(acc[3].x * rd, acc[3].y * rd);
    ((uint4*)g_aoh)[(size_t)i * 32 + lane] = o;
}

// ---------------- launch ----------------
extern "C" void kernel_launch(void* const* d_in, const int* in_sizes, int n_in,
                              void* d_out, int out_size) {
    const float* h   = (const float*)d_in[0];
    const int*   row = (const int*)d_in[1];
    const int*   col = (const int*)d_in[2];
    const float* Wq  = (const float*)d_in[3];
    const float* bq  = (const float*)d_in[4];
    const float* Wk  = (const float*)d_in[5];
    const float* bk  = (const float*)d_in[6];
    const float* Wv  = (const float*)d_in[7];
    const float* bv  = (const float*)d_in[8];
    const float* Wo  = (const float*)d_in[9];
    const float* bo  = (const float*)d_in[10];
    float* out = (float*)d_out;

    const int N = in_sizes[0] / HIDDEN;
    const int E = in_sizes[1];

    __half *pqh, *pkh, *pvh;
    int *pdeg;
    cudaGetSymbolAddress((void**)&pqh, g_qh);
    cudaGetSymbolAddress((void**)&pkh, g_kh);
    cudaGetSymbolAddress((void**)&pvh, g_vh);
    cudaGetSymbolAddress((void**)&pdeg, g_deg);

    static cudaStream_t s2 = nullptr;
    static cudaEvent_t evFork = nullptr, evJoin = nullptr;
    if (!s2) {
        cudaStreamCreateWithFlags(&s2, cudaStreamNonBlocking);
        cudaEventCreateWithFlags(&evFork, cudaEventDisableTiming);
        cudaEventCreateWithFlags(&evJoin, cudaEventDisableTiming);
    }

    // fork: CSR build on s2
    cudaEventRecord(evFork, 0);
    cudaStreamWaitEvent(s2, evFork, 0);
    cudaMemsetAsync(pdeg, 0, (size_t)N * sizeof(int), s2);
    count_deg_kernel<<<(E + 255) / 256, 256, 0, s2>>>(row, E);
    scan_kernel<<<1, 1024, 0, s2>>>(N);
    scatter_kernel<<<(E + 255) / 256, 256, 0, s2>>>(row, col, E);
    cudaEventRecord(evJoin, s2);

    // main: conversions, then QKV
    convert_a_kernel<<<(NTILES_PAD * 16 * 32 + 255) / 256, 256>>>(h, N);
    convert_w_kernel<<<(3 * 32 * 16 * 32 + 255) / 256, 256>>>(Wq, Wk, Wv);
    convert_wo_kernel<<<(32 * 16 * 32 + 255) / 256, 256>>>(Wo);

    const float scaling = 0.17677669529663687f;  // 32^-0.5
    dim3 gqkv((N + 127) / 128, HIDDEN / 128, 3);
    gemm_qkv_kernel<<<gqkv, 256>>>(bq, bk, bv, pqh, pkh, pvh, N, scaling);

    cudaStreamWaitEvent(0, evJoin, 0);
    attn_kernel<<<(N + 7) / 8, 256>>>(N);

    convert_ao_kernel<<<(NTILES_PAD * 16 * 32 + 255) / 256, 256>>>(N);

    dim3 go((N + 127) / 128, HIDDEN / 128, 1);
    gemm_oproj_kernel<<<go, 256>>>(bo, out, N);
}

// round 17
// speedup vs baseline: 2.0736x; 1.0134x over previous
#include <cuda_runtime.h>
#include <cuda_fp16.h>
#include <cstdint>

#define HIDDEN 256
#define HEADS 8
#define MAXN 50000
#define MAXE 800000
#define NTILES_PAD 3136          // ceil(50000/16) padded

// ---------------- scratch ----------------
// Head-major pair layout (per row of 256 halfs): word W (0..127) = half2 pair
//   (f, f+64), f = j*8 + h + (j>=8 ? 64 : 0), where h = W>>4, j = W&15.
// => lane l's uint4 (words 4l..4l+3) covers 8 feats ALL of head g = l>>2.
__device__ __half g_qh[(size_t)MAXN * HIDDEN];
__device__ __half g_kh[(size_t)MAXN * HIDDEN];
__device__ __half g_vh[(size_t)MAXN * HIDDEN];
// A (h) fragment order: cell c=(t*16+kc)*32+lane, 16B
__device__ __half g_af[(size_t)NTILES_PAD * 16 * 32 * 8];
// W (q,k,v) fragments, permuted rows: cell ((z,tn,kc,lane)), 8B
__device__ __half g_wf[3 * 32 * 16 * 32 * 4];
// attention-output fragments (written directly by attn epilogue)
__device__ __half g_aof[(size_t)NTILES_PAD * 16 * 32 * 8];
// Wo fragments with inverse k-permutation baked
__device__ __half g_wof[32 * 16 * 32 * 4];
__device__ int    g_deg[MAXN];
__device__ int    g_offs[MAXN + 1];
__device__ int    g_cursor[MAXN];
__device__ int    g_ccol[MAXE];

// feature for half-slot p (0..255): b=p&1, W=p>>1, h=W>>4, j=W&15
__device__ __host__ __forceinline__ int slot_feat(int p) {
    int b = p & 1, W = p >> 1, h = W >> 4, j = W & 15;
    return j * 8 + h + ((j >= 8) ? 64 : 0) + b * 64;
}

// ---------------- CSR build ----------------
__global__ void count_deg_kernel(const int* __restrict__ row, int e) {
    int i = blockIdx.x * blockDim.x + threadIdx.x;
    if (i < e) atomicAdd(&g_deg[row[i]], 1);
}

__global__ void scan_kernel(int n) {
    __shared__ int wsum[32];
    int lane = threadIdx.x & 31;
    int wid  = threadIdx.x >> 5;
    int carry = 0;
    for (int base = 0; base < n; base += 1024) {
        int i = base + (int)threadIdx.x;
        int v = (i < n) ? g_deg[i] : 0;
        int x = v;
        #pragma unroll
        for (int d = 1; d < 32; d <<= 1) {
            int y = __shfl_up_sync(0xffffffffu, x, d);
            if (lane >= d) x += y;
        }
        if (lane == 31) wsum[wid] = x;
        __syncthreads();
        if (wid == 0) {
            int wv = wsum[lane];
            #pragma unroll
            for (int d = 1; d < 32; d <<= 1) {
                int y = __shfl_up_sync(0xffffffffu, wv, d);
                if (lane >= d) wv += y;
            }
            wsum[lane] = wv;
        }
        __syncthreads();
        int inc = x + (wid > 0 ? wsum[wid - 1] : 0) + carry;
        if (i < n) {
            int excl = inc - v;
            g_offs[i]   = excl;
            g_cursor[i] = excl;
        }
        carry += wsum[31];
        __syncthreads();
    }
    if (threadIdx.x == 0) g_offs[n] = carry;
}

__global__ void scatter_kernel(const int* __restrict__ row, const int* __restrict__ col, int e) {
    int i = blockIdx.x * blockDim.x + threadIdx.x;
    if (i < e) {
        int slot = atomicAdd(&g_cursor[row[i]], 1);
        g_ccol[slot] = col[i];
    }
}

// ---------------- helpers ----------------
__device__ __forceinline__ uint32_t packh2(float x, float y) {
    __half2 h = __halves2half2(__float2half_rn(x), __float2half_rn(y));
    return *(uint32_t*)&h;
}

#define MMA_F16(ACC, AV, B0, B1)                                           \
    asm volatile(                                                          \
        "mma.sync.aligned.m16n8k16.row.col.f32.f16.f16.f32 "              \
        "{%0,%1,%2,%3}, {%4,%5,%6,%7}, {%8,%9}, {%0,%1,%2,%3};"           \
        : "+f"(ACC[0]), "+f"(ACC[1]), "+f"(ACC[2]), "+f"(ACC[3])          \
        : "r"(AV.x), "r"(AV.y), "r"(AV.z), "r"(AV.w),                     \
          "r"(B0), "r"(B1))

#define CP_ASYNC16(dst, src)                                               \
    asm volatile("cp.async.ca.shared.global [%0], [%1], 16;"              \
                 :: "r"(dst), "l"(src))
#define CP_ASYNC8(dst, src)                                                \
    asm volatile("cp.async.ca.shared.global [%0], [%1], 8;"               \
                 :: "r"(dst), "l"(src))
#define CP_COMMIT()  asm volatile("cp.async.commit_group;" ::: "memory")
#define CP_WAIT2()   asm volatile("cp.async.wait_group 2;" ::: "memory")

// ---------------- merged conversion kernel ----------------
// ranges: [0, NA): A frags  | [NA, NA+NW): qkv W frags | [NA+NW, NA+NW+NWO): Wo frags
#define CONV_NA (NTILES_PAD * 16 * 32)
#define CONV_NW (3 * 32 * 16 * 32)
#define CONV_NWO (32 * 16 * 32)

__global__ void convert_all_kernel(const float* __restrict__ A, int n,
                                   const float* __restrict__ Wq,
                                   const float* __restrict__ Wk,
                                   const float* __restrict__ Wv,
                                   const float* __restrict__ Wo) {
    int idx = blockIdx.x * blockDim.x + threadIdx.x;
    if (idx < CONV_NA) {
        int c = idx;
        int lane = c & 31;
        int kc   = (c >> 5) & 15;
        int t    = c >> 9;
        int g    = lane >> 2;
        int tig  = lane & 3;
        int r0 = t * 16 + g, r1 = r0 + 8;
        int kb = kc * 16 + 2 * tig;
        float2 a00 = make_float2(0.f, 0.f), a01 = a00, a10 = a00, a11 = a00;
        if (r0 < n) {
            a00 = *(const float2*)(A + (size_t)r0 * HIDDEN + kb);
            a01 = *(const float2*)(A + (size_t)r0 * HIDDEN + kb + 8);
        }
        if (r1 < n) {
            a10 = *(const float2*)(A + (size_t)r1 * HIDDEN + kb);
            a11 = *(const float2*)(A + (size_t)r1 * HIDDEN + kb + 8);
        }
        uint4 o;
        o.x = packh2(a00.x, a00.y);
        o.y = packh2(a10.x, a10.y);
        o.z = packh2(a01.x, a01.y);
        o.w = packh2(a11.x, a11.y);
        ((uint4*)g_af)[c] = o;
    } else if (idx < CONV_NA + CONV_NW) {
        int c = idx - CONV_NA;
        int lane = c & 31;
        int kc   = (c >> 5) & 15;
        int tn   = (c >> 9) & 31;
        int z    = c >> 14;
        int g    = lane >> 2;
        int tig  = lane & 3;
        int p  = tn * 8 + g;
        int wr = slot_feat(p);
        const float* W = (z == 0) ? Wq : (z == 1) ? Wk : Wv;
        int kb = kc * 16 + 2 * tig;
        float2 f0 = *(const float2*)(W + (size_t)wr * HIDDEN + kb);
        float2 f1 = *(const float2*)(W + (size_t)wr * HIDDEN + kb + 8);
        uint2 o;
        o.x = packh2(f0.x, f0.y);
        o.y = packh2(f1.x, f1.y);
        ((uint2*)g_wf)[c] = o;
    } else if (idx < CONV_NA + CONV_NW + CONV_NWO) {
        int c = idx - CONV_NA - CONV_NW;
        int lane = c & 31;
        int kc   = (c >> 5) & 15;
        int tn   = c >> 9;
        int g    = lane >> 2;
        int tig  = lane & 3;
        int col = tn * 8 + g;
        const float* Wr = Wo + (size_t)col * HIDDEN;
        int p0 = kc * 16 + 2 * tig;
        int fA = slot_feat(p0);
        int p1 = p0 + 8;
        int fB = slot_feat(p1);
        uint2 o;
        o.x = packh2(Wr[fA], Wr[fA + 64]);
        o.y = packh2(Wr[fB], Wr[fB + 64]);
        ((uint2*)g_wof)[c] = o;
    }
}

// ================ fragment cp.async GEMM =====================
#define STG_SZ 8192    // A 4KB + B 4KB

// QKV: fp16 head-major epilogue
__global__ void __launch_bounds__(256, 2) gemm_qkv_kernel(
    const float* __restrict__ b0_, const float* __restrict__ b1_, const float* __restrict__ b2_,
    __half* __restrict__ QH, __half* __restrict__ KH, __half* __restrict__ VH,
    int M, float scale0)
{
    __shared__ __align__(16) unsigned char sm[4 * STG_SZ];

    const int z = blockIdx.z;
    const float* bias = (z == 0) ? b0_ : (z == 1) ? b1_ : b2_;
    __half* H         = (z == 0) ? QH : (z == 1) ? KH : VH;
    const float scale = (z == 0) ? scale0 : 1.f;

    const int tid  = threadIdx.x;
    const int lane = tid & 31;
    const int warp = tid >> 5;
    const int g    = lane >> 2;
    const int tig  = lane & 3;
    const int wm   = (warp >> 1) * 32;
    const int wn   = (warp & 1) * 64;

    const int m0 = blockIdx.x * 128;
    const int n0 = blockIdx.y * 128;

    const uint32_t smbase = (uint32_t)__cvta_generic_to_shared(sm);
    const int ftr = warp;

    const char* afbase = (const char*)g_af + ((size_t)((m0 >> 4) + ftr)) * 8192 + lane * 16;
    const char* wfbase = (const char*)g_wf + (size_t)z * 131072;
    const int tng0 = (n0 >> 3) + ftr;
    const char* wf0 = wfbase + (size_t)tng0 * 4096 + lane * 8;
    const char* wf1 = wfbase + (size_t)(tng0 + 8) * 4096 + lane * 8;

    float acc[2][8][4];
    #pragma unroll
    for (int mt = 0; mt < 2; mt++)
        #pragma unroll
        for (int nt = 0; nt < 8; nt++)
            #pragma unroll
            for (int r = 0; r < 4; r++) acc[mt][nt][r] = 0.f;

    #define FILL(s, kc) do {                                               \
        uint32_t dA = smbase + (s) * STG_SZ + ftr * 512 + lane * 16;       \
        CP_ASYNC16(dA, afbase + (kc) * 512);                               \
        uint32_t dB0 = smbase + (s) * STG_SZ + 4096 + ftr * 256 + lane * 8;\
        CP_ASYNC8(dB0, wf0 + (kc) * 256);                                  \
        uint32_t dB1 = dB0 + 2048;                                         \
        CP_ASYNC8(dB1, wf1 + (kc) * 256);                                  \
        CP_COMMIT();                                                       \
    } while (0)

    FILL(0, 0);
    FILL(1, 1);
    FILL(2, 2);

    #pragma unroll 1
    for (int it = 0; it < 16; it++) {
        CP_WAIT2();
        __syncthreads();
        {
            const unsigned char* st = sm + (it & 3) * STG_SZ;
            uint4 ah[2];
            #pragma unroll
            for (int mt = 0; mt < 2; mt++) {
                int tr = (wm >> 4) + mt;
                ah[mt] = *(const uint4*)(st + tr * 512 + lane * 16);
            }
            #pragma unroll
            for (int nt = 0; nt < 8; nt++) {
                int tn = (wn >> 3) + nt;
                uint2 bh = *(const uint2*)(st + 4096 + tn * 256 + lane * 8);
                MMA_F16(acc[0][nt], ah[0], bh.x, bh.y);
                MMA_F16(acc[1][nt], ah[1], bh.x, bh.y);
            }
        }
        if (it + 3 < 16) {
            FILL((it + 3) & 3, it + 3);
        } else {
            CP_COMMIT();
        }
    }
    #undef FILL

    #pragma unroll
    for (int mt = 0; mt < 2; mt++) {
        int r0 = m0 + wm + mt * 16 + g;
        #pragma unroll
        for (int nt = 0; nt < 8; nt++) {
            int p = n0 + wn + nt * 8 + 2 * tig;
            int f0 = slot_feat(p);
            float bx = bias[f0];
            float by = bias[f0 + 64];
            if (r0 < M) {
                *(__half2*)(H + (size_t)r0 * HIDDEN + p) =
                    __halves2half2(__float2half_rn((acc[mt][nt][0] + bx) * scale),
                                   __float2half_rn((acc[mt][nt][1] + by) * scale));
            }
            if (r0 + 8 < M) {
                *(__half2*)(H + (size_t)(r0 + 8) * HIDDEN + p) =
                    __halves2half2(__float2half_rn((acc[mt][nt][2] + bx) * scale),
                                   __float2half_rn((acc[mt][nt][3] + by) * scale));
            }
        }
    }
}

// O-proj: same pipeline, fp32 epilogue
__global__ void __launch_bounds__(256, 2) gemm_oproj_kernel(
    const float* __restrict__ bias, float* __restrict__ C, int M)
{
    __shared__ __align__(16) unsigned char sm[4 * STG_SZ];

    const int tid  = threadIdx.x;
    const int lane = tid & 31;
    const int warp = tid >> 5;
    const int g    = lane >> 2;
    const int tig  = lane & 3;
    const int wm   = (warp >> 1) * 32;
    const int wn   = (warp & 1) * 64;

    const int m0 = blockIdx.x * 128;
    const int n0 = blockIdx.y * 128;

    const uint32_t smbase = (uint32_t)__cvta_generic_to_shared(sm);
    const int ftr = warp;

    const char* afbase = (const char*)g_aof + ((size_t)((m0 >> 4) + ftr)) * 8192 + lane * 16;
    const int tng0 = (n0 >> 3) + ftr;
    const char* wf0 = (const char*)g_wof + (size_t)tng0 * 4096 + lane * 8;
    const char* wf1 = (const char*)g_wof + (size_t)(tng0 + 8) * 4096 + lane * 8;

    float acc[2][8][4];
    #pragma unroll
    for (int mt = 0; mt < 2; mt++)
        #pragma unroll
        for (int nt = 0; nt < 8; nt++)
            #pragma unroll
            for (int r = 0; r < 4; r++) acc[mt][nt][r] = 0.f;

    #define FILL(s, kc) do {                                               \
        uint32_t dA = smbase + (s) * STG_SZ + ftr * 512 + lane * 16;       \
        CP_ASYNC16(dA, afbase + (kc) * 512);                               \
        uint32_t dB0 = smbase + (s) * STG_SZ + 4096 + ftr * 256 + lane * 8;\
        CP_ASYNC8(dB0, wf0 + (kc) * 256);                                  \
        uint32_t dB1 = dB0 + 2048;                                         \
        CP_ASYNC8(dB1, wf1 + (kc) * 256);                                  \
        CP_COMMIT();                                                       \
    } while (0)

    FILL(0, 0);
    FILL(1, 1);
    FILL(2, 2);

    #pragma unroll 1
    for (int it = 0; it < 16; it++) {
        CP_WAIT2();
        __syncthreads();
        {
            const unsigned char* st = sm + (it & 3) * STG_SZ;
            uint4 ah[2];
            #pragma unroll
            for (int mt = 0; mt < 2; mt++) {
                int tr = (wm >> 4) + mt;
                ah[mt] = *(const uint4*)(st + tr * 512 + lane * 16);
            }
            #pragma unroll
            for (int nt = 0; nt < 8; nt++) {
                int tn = (wn >> 3) + nt;
                uint2 bh = *(const uint2*)(st + 4096 + tn * 256 + lane * 8);
                MMA_F16(acc[0][nt], ah[0], bh.x, bh.y);
                MMA_F16(acc[1][nt], ah[1], bh.x, bh.y);
            }
        }
        if (it + 3 < 16) {
            FILL((it + 3) & 3, it + 3);
        } else {
            CP_COMMIT();
        }
    }
    #undef FILL

    #pragma unroll
    for (int mt = 0; mt < 2; mt++) {
        int r0 = m0 + wm + mt * 16 + g;
        #pragma unroll
        for (int nt = 0; nt < 8; nt++) {
            int c = n0 + wn + nt * 8 + 2 * tig;
            float bx = bias[c], by = bias[c + 1];
            if (r0 < M) {
                float2 o0;
                o0.x = acc[mt][nt][0] + bx;
                o0.y = acc[mt][nt][1] + by;
                *(float2*)(C + (size_t)r0 * HIDDEN + c) = o0;
            }
            if (r0 + 8 < M) {
                float2 o1;
                o1.x = acc[mt][nt][2] + bx;
                o1.y = acc[mt][nt][3] + by;
                *(float2*)(C + (size_t)(r0 + 8) * HIDDEN + c) = o1;
            }
        }
    }
}

// ---------------- attention: head-major loads, fragment-direct output ------
__global__ void __launch_bounds__(256) attn_kernel(int n) {
    int gw   = (blockIdx.x * blockDim.x + threadIdx.x) >> 5;
    int lane = threadIdx.x & 31;
    if (gw >= n) return;
    const int i = gw;
    const int start = g_offs[i];
    const int end   = g_offs[i + 1];

    const uint4* QB = (const uint4*)g_qh;
    const uint4* KB = (const uint4*)g_kh;
    const uint4* VB = (const uint4*)g_vh;

    float2 q[4];
    {
        uint4 qv = QB[(size_t)i * 32 + lane];
        q[0] = __half22float2(*(__half2*)&qv.x);
        q[1] = __half22float2(*(__half2*)&qv.y);
        q[2] = __half22float2(*(__half2*)&qv.z);
        q[3] = __half22float2(*(__half2*)&qv.w);
    }

    float m = __int_as_float(0xff800000);
    float d = 0.f;
    float2 acc[4] = {};

    int p = start;
    for (; p + 7 < end; p += 8) {
        int cn[8];
        #pragma unroll
        for (int e = 0; e < 8; e++) cn[e] = g_ccol[p + e];

        uint4 kv[8];
        #pragma unroll
        for (int e = 0; e < 8; e++) kv[e] = __ldg(&KB[(size_t)cn[e] * 32 + lane]);

        float s[8];
        #pragma unroll
        for (int e = 0; e < 8; e++) {
            float2 k0 = __half22float2(*(__half2*)&kv[e].x);
            float2 k1 = __half22float2(*(__half2*)&kv[e].y);
            float2 k2 = __half22float2(*(__half2*)&kv[e].z);
            float2 k3 = __half22float2(*(__half2*)&kv[e].w);
            s[e] = q[0].x * k0.x + q[0].y * k0.y
                 + q[1].x * k1.x + q[1].y * k1.y
                 + q[2].x * k2.x + q[2].y * k2.y
                 + q[3].x * k3.x + q[3].y * k3.y;
        }
        #pragma unroll
        for (int e = 0; e < 8; e++) {
            s[e] += __shfl_xor_sync(0xffffffffu, s[e], 1);
            s[e] += __shfl_xor_sync(0xffffffffu, s[e], 2);
        }

        float m2 = m;
        #pragma unroll
        for (int e = 0; e < 8; e++) m2 = fmaxf(m2, s[e]);
        float cf = __expf(m - m2);
        float w[8], sw = 0.f;
        #pragma unroll
        for (int e = 0; e < 8; e++) { w[e] = __expf(s[e] - m2); sw += w[e]; }
        d = d * cf + sw;
        m = m2;

        #pragma unroll
        for (int c = 0; c < 4; c++) { acc[c].x *= cf; acc[c].y *= cf; }
        #pragma unroll
        for (int e = 0; e < 8; e++) {
            uint4 vv = __ldg(&VB[(size_t)cn[e] * 32 + lane]);
            float2 v0 = __half22float2(*(__half2*)&vv.x);
            float2 v1 = __half22float2(*(__half2*)&vv.y);
            float2 v2 = __half22float2(*(__half2*)&vv.z);
            float2 v3 = __half22float2(*(__half2*)&vv.w);
            acc[0].x += w[e] * v0.x; acc[0].y += w[e] * v0.y;
            acc[1].x += w[e] * v1.x; acc[1].y += w[e] * v1.y;
            acc[2].x += w[e] * v2.x; acc[2].y += w[e] * v2.y;
            acc[3].x += w[e] * v3.x; acc[3].y += w[e] * v3.y;
        }
    }
    for (; p < end; p++) {
        int c0 = g_ccol[p];
        uint4 kv = __ldg(&KB[(size_t)c0 * 32 + lane]);
        float2 k0 = __half22float2(*(__half2*)&kv.x);
        float2 k1 = __half22float2(*(__half2*)&kv.y);
        float2 k2 = __half22float2(*(__half2*)&kv.z);
        float2 k3 = __half22float2(*(__half2*)&kv.w);
        float s0 = q[0].x * k0.x + q[0].y * k0.y
                 + q[1].x * k1.x + q[1].y * k1.y
                 + q[2].x * k2.x + q[2].y * k2.y
                 + q[3].x * k3.x + q[3].y * k3.y;
        s0 += __shfl_xor_sync(0xffffffffu, s0, 1);
        s0 += __shfl_xor_sync(0xffffffffu, s0, 2);
        float m2 = fmaxf(m, s0);
        float cf = __expf(m - m2);
        float w0 = __expf(s0 - m2);
        d = d * cf + w0;
        m = m2;
        uint4 vv = __ldg(&VB[(size_t)c0 * 32 + lane]);
        float2 v0 = __half22float2(*(__half2*)&vv.x);
        float2 v1 = __half22float2(*(__half2*)&vv.y);
        float2 v2 = __half22float2(*(__half2*)&vv.z);
        float2 v3 = __half22float2(*(__half2*)&vv.w);
        acc[0].x = acc[0].x * cf + w0 * v0.x; acc[0].y = acc[0].y * cf + w0 * v0.y;
        acc[1].x = acc[1].x * cf + w0 * v1.x; acc[1].y = acc[1].y * cf + w0 * v1.y;
        acc[2].x = acc[2].x * cf + w0 * v2.x; acc[2].y = acc[2].y * cf + w0 * v2.y;
        acc[3].x = acc[3].x * cf + w0 * v3.x; acc[3].y = acc[3].y * cf + w0 * v3.y;
    }

    float rd = (end > start) ? 1.f / d : 0.f;
    // fragment-direct store: word w = 4*lane + j of row i ->
    //   kc = w>>3, rem = w&7, tig = rem&3, hi4 = rem>>2
    //   cell = (t*16+kc)*32 + (i&7)*4 + tig ; slot = hi4*2 + ((i>>3)&1)
    uint32_t wv[4];
    wv[0] = packh2(acc[0].x * rd, acc[0].y * rd);
    wv[1] = packh2(acc[1].x * rd, acc[1].y * rd);
    wv[2] = packh2(acc[2].x * rd, acc[2].y * rd);
    wv[3] = packh2(acc[3].x * rd, acc[3].y * rd);
    uint32_t* AOF = (uint32_t*)g_aof;
    size_t t = (size_t)(i >> 4);
    int fl_base = (i & 7) * 4;
    int rowslot = (i >> 3) & 1;
    #pragma unroll
    for (int j = 0; j < 4; j++) {
        int w = 4 * lane + j;
        int kc  = w >> 3;
        int rem = w & 7;
        int tig = rem & 3;
        int hi4 = rem >> 2;
        int slot = hi4 * 2 + rowslot;
        size_t cell = (t * 16 + kc) * 32 + fl_base + tig;
        AOF[cell * 4 + slot] = wv[j];
    }
}

// ---------------- launch ----------------
extern "C" void kernel_launch(void* const* d_in, const int* in_sizes, int n_in,
                              void* d_out, int out_size) {
    const float* h   = (const float*)d_in[0];
    const int*   row = (const int*)d_in[1];
    const int*   col = (const int*)d_in[2];
    const float* Wq  = (const float*)d_in[3];
    const float* bq  = (const float*)d_in[4];
    const float* Wk  = (const float*)d_in[5];
    const float* bk  = (const float*)d_in[6];
    const float* Wv  = (const float*)d_in[7];
    const float* bv  = (const float*)d_in[8];
    const float* Wo  = (const float*)d_in[9];
    const float* bo  = (const float*)d_in[10];
    float* out = (float*)d_out;

    const int N = in_sizes[0] / HIDDEN;
    const int E = in_sizes[1];

    __half *pqh, *pkh, *pvh, *paof;
    int *pdeg;
    cudaGetSymbolAddress((void**)&pqh, g_qh);
    cudaGetSymbolAddress((void**)&pkh, g_kh);
    cudaGetSymbolAddress((void**)&pvh, g_vh);
    cudaGetSymbolAddress((void**)&paof, g_aof);
    cudaGetSymbolAddress((void**)&pdeg, g_deg);

    static cudaStream_t s2 = nullptr;
    static cudaEvent_t evFork = nullptr, evJoin = nullptr;
    if (!s2) {
        cudaStreamCreateWithFlags(&s2, cudaStreamNonBlocking);
        cudaEventCreateWithFlags(&evFork, cudaEventDisableTiming);
        cudaEventCreateWithFlags(&evJoin, cudaEventDisableTiming);
    }

    // fork: CSR build on s2
    cudaEventRecord(evFork, 0);
    cudaStreamWaitEvent(s2, evFork, 0);
    cudaMemsetAsync(pdeg, 0, (size_t)N * sizeof(int), s2);
    count_deg_kernel<<<(E + 255) / 256, 256, 0, s2>>>(row, E);
    scan_kernel<<<1, 1024, 0, s2>>>(N);
    scatter_kernel<<<(E + 255) / 256, 256, 0, s2>>>(row, col, E);
    cudaEventRecord(evJoin, s2);

    // zero aof padding tiles (rows >= N reachable by O-proj's last CTA band)
    {
        int tstart = N >> 4;                       // first (possibly partial) tile
        int tcount = 16;
        if (tstart + tcount > NTILES_PAD) tcount = NTILES_PAD - tstart;
        if (tcount > 0)
            cudaMemsetAsync((char*)paof + (size_t)tstart * 8192,
                            0, (size_t)tcount * 8192, 0);
    }

    // merged conversions
    convert_all_kernel<<<(CONV_NA + CONV_NW + CONV_NWO + 255) / 256, 256>>>(
        h, N, Wq, Wk, Wv, Wo);

    const float scaling = 0.17677669529663687f;  // 32^-0.5
    dim3 gqkv((N + 127) / 128, HIDDEN / 128, 3);
    gemm_qkv_kernel<<<gqkv, 256>>>(bq, bk, bv, pqh, pkh, pvh, N, scaling);

    cudaStreamWaitEvent(0, evJoin, 0);
    attn_kernel<<<(N + 7) / 8, 256>>>(N);

    dim3 go((N + 127) / 128, HIDDEN / 128, 1);
    gemm_oproj_kernel<<<go, 256>>>(bo, out, N);
}